// round 3
// baseline (speedup 1.0000x reference)
#include <cuda_runtime.h>
#include <cuda_bf16.h>
#include <math_constants.h>

// Problem constants
#define BB 2
#define LL 2048
#define DD 1024
#define HH 16
#define DKK 64
#define MM (BB * LL)          // 4096 rows for projections

using ull = unsigned long long;

// ---------------------------------------------------------------------------
// Packed f32x2 helpers (Blackwell full-rate FMA path; ptxas never emits these)
// ---------------------------------------------------------------------------
__device__ __forceinline__ ull ffma2(ull a, ull b, ull c) {
    ull d;
    asm("fma.rn.f32x2 %0, %1, %2, %3;" : "=l"(d) : "l"(a), "l"(b), "l"(c));
    return d;
}
__device__ __forceinline__ ull fmul2(ull a, ull b) {
    ull d;
    asm("mul.rn.f32x2 %0, %1, %2;" : "=l"(d) : "l"(a), "l"(b));
    return d;
}
__device__ __forceinline__ ull fadd2(ull a, ull b) {
    ull d;
    asm("add.rn.f32x2 %0, %1, %2;" : "=l"(d) : "l"(a), "l"(b));
    return d;
}
__device__ __forceinline__ ull pack2(float x, float y) {
    ull d;
    unsigned xi = __float_as_uint(x), yi = __float_as_uint(y);
    asm("mov.b64 %0, {%1, %2};" : "=l"(d) : "r"(xi), "r"(yi));
    return d;
}
__device__ __forceinline__ ull dup2(float x) {
    ull d;
    unsigned xi = __float_as_uint(x);
    asm("mov.b64 %0, {%1, %1};" : "=l"(d) : "r"(xi));
    return d;
}
__device__ __forceinline__ float2 unpack2(ull a) {
    unsigned l, h;
    asm("mov.b64 {%0, %1}, %2;" : "=r"(l), "=r"(h) : "l"(a));
    return make_float2(__uint_as_float(l), __uint_as_float(h));
}
__device__ __forceinline__ float sum2(ull a) {
    float2 f = unpack2(a);
    return f.x + f.y;
}

// ---------------------------------------------------------------------------
// Scratch (device globals — no allocation allowed in kernel_launch)
// ---------------------------------------------------------------------------
__device__ float g_Q[BB * HH * LL * DKK];     // [b][h][l][d]
__device__ float g_K[BB * HH * LL * DKK];
__device__ float g_V[BB * HH * LL * DKK];
__device__ float g_attn[MM * DD];             // [b*L + l][h*64 + d]

// ---------------------------------------------------------------------------
// GEMM (NT) body with FFMA2: C[M,N] = A[M,K]*W[N,K]^T + bias[N]
// 128x128 tile, 16 k-slice, 8x8 microtile (as 8x4 packed pairs), 256 thr.
// A is stored DUPLICATED in smem (float2{a,a}) so FFMA2 dup-operands load
// directly with no per-iteration packing.
// ---------------------------------------------------------------------------
__device__ __forceinline__ void gemm_tile_f32x2(
    const float* __restrict__ A, const float* __restrict__ W,
    ull (&acc)[8][4],
    float2 (*As2)[128], float (*Bs)[128])
{
    const int K = DD;
    int tid = threadIdx.x;
    int row0 = blockIdx.y * 128;
    int col0 = blockIdx.x * 128;
    int tx = tid & 15;
    int ty = tid >> 4;
    int lr = tid >> 2;
    int lc = (tid & 3) * 4;

    const float* Aptr = A + (size_t)(row0 + lr) * K + lc;
    const float* Wptr = W + (size_t)(col0 + lr) * K + lc;

#pragma unroll
    for (int u = 0; u < 8; u++)
#pragma unroll
        for (int v = 0; v < 4; v++) acc[u][v] = 0ull;

    for (int kt = 0; kt < K; kt += 16) {
        float4 a0 = *(const float4*)(Aptr + kt);
        float4 a1 = *(const float4*)(Aptr + (size_t)64 * K + kt);
        float4 b0 = *(const float4*)(Wptr + kt);
        float4 b1 = *(const float4*)(Wptr + (size_t)64 * K + kt);

        __syncthreads();
        As2[lc + 0][lr] = make_float2(a0.x, a0.x);
        As2[lc + 1][lr] = make_float2(a0.y, a0.y);
        As2[lc + 2][lr] = make_float2(a0.z, a0.z);
        As2[lc + 3][lr] = make_float2(a0.w, a0.w);
        As2[lc + 0][lr + 64] = make_float2(a1.x, a1.x);
        As2[lc + 1][lr + 64] = make_float2(a1.y, a1.y);
        As2[lc + 2][lr + 64] = make_float2(a1.z, a1.z);
        As2[lc + 3][lr + 64] = make_float2(a1.w, a1.w);
        Bs[lc + 0][lr] = b0.x; Bs[lc + 1][lr] = b0.y;
        Bs[lc + 2][lr] = b0.z; Bs[lc + 3][lr] = b0.w;
        Bs[lc + 0][lr + 64] = b1.x; Bs[lc + 1][lr + 64] = b1.y;
        Bs[lc + 2][lr + 64] = b1.z; Bs[lc + 3][lr + 64] = b1.w;
        __syncthreads();

#pragma unroll
        for (int kk = 0; kk < 16; kk++) {
            // duplicated A pairs: 4x LDS.128 -> 8 dup-pairs {a_u, a_u}
            const ulonglong2* ad = reinterpret_cast<const ulonglong2*>(&As2[kk][ty * 8]);
            ulonglong2 ax = ad[0], ay = ad[1], az = ad[2], aw = ad[3];
            ull adup[8] = {ax.x, ax.y, ay.x, ay.y, az.x, az.y, aw.x, aw.y};
            // natural B pairs: 2x LDS.128 -> 4 pairs {b_{2v}, b_{2v+1}}
            const ulonglong2* bd = reinterpret_cast<const ulonglong2*>(&Bs[kk][tx * 8]);
            ulonglong2 bx = bd[0], by = bd[1];
            ull b2[4] = {bx.x, bx.y, by.x, by.y};
#pragma unroll
            for (int u = 0; u < 8; u++)
#pragma unroll
                for (int v = 0; v < 4; v++)
                    acc[u][v] = ffma2(adup[u], b2[v], acc[u][v]);
        }
    }
}

// ---------------------------------------------------------------------------
// Fused QKV projection: gridDim.z selects Q/K/V. Scatters into [b][h][l][d].
// ---------------------------------------------------------------------------
__global__ __launch_bounds__(256, 2) void qkv_gemm(
    const float* __restrict__ xq, const float* __restrict__ xk,
    const float* __restrict__ xv,
    const float* __restrict__ wq, const float* __restrict__ wk,
    const float* __restrict__ wv,
    const float* __restrict__ bq, const float* __restrict__ bk,
    const float* __restrict__ bv)
{
    __shared__ float2 As2[16][128];
    __shared__ float  Bs[16][128];

    int z = blockIdx.z;
    const float* A    = (z == 0) ? xq : (z == 1) ? xk : xv;
    const float* W    = (z == 0) ? wq : (z == 1) ? wk : wv;
    const float* bias = (z == 0) ? bq : (z == 1) ? bk : bv;
    float* dst        = (z == 0) ? g_Q : (z == 1) ? g_K : g_V;

    ull acc[8][4];
    gemm_tile_f32x2(A, W, acc, As2, Bs);

    int tid = threadIdx.x;
    int row0 = blockIdx.y * 128;
    int col0 = blockIdx.x * 128;
    int tx = tid & 15;
    int ty = tid >> 4;

#pragma unroll
    for (int u = 0; u < 8; u++) {
        int r = row0 + ty * 8 + u;
        int bb = r >> 11;
        int l  = r & 2047;
#pragma unroll
        for (int v = 0; v < 4; v++) {
            float2 p = unpack2(acc[u][v]);
            int c0 = col0 + tx * 8 + 2 * v;
            int h0 = c0 >> 6, d0 = c0 & 63;
            int c1 = c0 + 1;
            int h1 = c1 >> 6, d1 = c1 & 63;
            dst[(((size_t)(bb * HH + h0)) * LL + l) * DKK + d0] = p.x + bias[c0];
            dst[(((size_t)(bb * HH + h1)) * LL + l) * DKK + d1] = p.y + bias[c1];
        }
    }
}

// ---------------------------------------------------------------------------
// Output projection: reads g_attn, writes row-major d_out.
// ---------------------------------------------------------------------------
__global__ __launch_bounds__(256, 2) void out_gemm(
    const float* __restrict__ wo, const float* __restrict__ bo,
    float* __restrict__ Cout)
{
    __shared__ float2 As2[16][128];
    __shared__ float  Bs[16][128];

    ull acc[8][4];
    gemm_tile_f32x2(g_attn, wo, acc, As2, Bs);

    int tid = threadIdx.x;
    int row0 = blockIdx.y * 128;
    int col0 = blockIdx.x * 128;
    int tx = tid & 15;
    int ty = tid >> 4;

#pragma unroll
    for (int u = 0; u < 8; u++) {
        int r = row0 + ty * 8 + u;
#pragma unroll
        for (int v = 0; v < 4; v++) {
            float2 p = unpack2(acc[u][v]);
            int c = col0 + tx * 8 + 2 * v;
            Cout[(size_t)r * DD + c]     = p.x + bo[c];
            Cout[(size_t)r * DD + c + 1] = p.y + bo[c + 1];
        }
    }
}

// ---------------------------------------------------------------------------
// Flash attention, fp32 (FFMA2), causal. 1 thread = 1 query row.
// Block: 128 threads (128 q rows). K/V tiles 64x64 in smem; rows read as
// ulonglong2 (LDS.128 broadcast). Heavy q-tiles launched first.
// ---------------------------------------------------------------------------
__global__ __launch_bounds__(128) void flash_attn()
{
    __shared__ __align__(16) float Ks[64][64];
    __shared__ __align__(16) float Vs[64][64];

    int bh  = blockIdx.y;                           // 0..31 (= b*16 + h)
    int q0  = ((int)gridDim.x - 1 - (int)blockIdx.x) * 128;  // heavy-first
    int tid = threadIdx.x;
    int row = q0 + tid;

    const float* Qrow = g_Q + ((size_t)bh * LL + row) * DKK;
    const float* Kbh  = g_K + (size_t)bh * LL * DKK;
    const float* Vbh  = g_V + (size_t)bh * LL * DKK;

    const float inv_scale = 0.125f;                 // 1/sqrt(64)

    ull q2[32];
    {
        const float4* Qr4 = (const float4*)Qrow;
#pragma unroll
        for (int i = 0; i < 16; i++) {
            float4 v = Qr4[i];
            q2[2 * i + 0] = pack2(v.x * inv_scale, v.y * inv_scale);
            q2[2 * i + 1] = pack2(v.z * inv_scale, v.w * inv_scale);
        }
    }

    ull o2[32];
#pragma unroll
    for (int i = 0; i < 32; i++) o2[i] = 0ull;
    float m = -CUDART_INF_F;
    float l = 0.0f;

    int nkt = (q0 >> 6) + 2;                        // key tiles covering [0, q0+127]

    for (int kt = 0; kt < nkt; kt++) {
        __syncthreads();
        for (int i = tid; i < 64 * 16; i += 128) {
            int r  = i >> 4;
            int c4 = (i & 15) * 4;
            size_t goff = ((size_t)(kt * 64 + r)) * DKK + c4;
            *(float4*)&Ks[r][c4] = *(const float4*)(Kbh + goff);
            *(float4*)&Vs[r][c4] = *(const float4*)(Vbh + goff);
        }
        __syncthreads();

        int kbase = kt * 64;
        int jmax  = row - kbase + 1;                // causal
        if (jmax > 64) jmax = 64;

        for (int j = 0; j < jmax; j++) {
            const ulonglong2* Kr = reinterpret_cast<const ulonglong2*>(&Ks[j][0]);
            ull sa = 0ull, sb = 0ull;
#pragma unroll
            for (int i = 0; i < 16; i++) {
                ulonglong2 kk = Kr[i];
                sa = ffma2(q2[2 * i + 0], kk.x, sa);
                sb = ffma2(q2[2 * i + 1], kk.y, sb);
            }
            float s = sum2(fadd2(sa, sb));

            if (s > m) {                            // rare after warmup
                float c = __expf(m - s);
                m = s;
                l *= c;
                ull cd = dup2(c);
#pragma unroll
                for (int i = 0; i < 32; i++) o2[i] = fmul2(cd, o2[i]);
            }
            float p = __expf(s - m);
            l += p;
            ull pd = dup2(p);
            const ulonglong2* Vr = reinterpret_cast<const ulonglong2*>(&Vs[j][0]);
#pragma unroll
            for (int i = 0; i < 16; i++) {
                ulonglong2 vv = Vr[i];
                o2[2 * i + 0] = ffma2(pd, vv.x, o2[2 * i + 0]);
                o2[2 * i + 1] = ffma2(pd, vv.y, o2[2 * i + 1]);
            }
        }
    }

    float inv_l = 1.0f / l;
    int bb = bh >> 4;
    int h  = bh & 15;
    float* orow = g_attn + ((size_t)(bb * LL + row)) * DD + h * DKK;
#pragma unroll
    for (int i = 0; i < 16; i++) {
        float2 p0 = unpack2(o2[2 * i + 0]);
        float2 p1 = unpack2(o2[2 * i + 1]);
        *(float4*)(orow + 4 * i) =
            make_float4(p0.x * inv_l, p0.y * inv_l, p1.x * inv_l, p1.y * inv_l);
    }
}

// ---------------------------------------------------------------------------
// Launcher
// ---------------------------------------------------------------------------
extern "C" void kernel_launch(void* const* d_in, const int* in_sizes, int n_in,
                              void* d_out, int out_size)
{
    const float* query = (const float*)d_in[0];
    const float* key_  = (const float*)d_in[1];
    const float* value = (const float*)d_in[2];
    // d_in[3] = mask (causal; implemented structurally, not read)
    const float* w_q = (const float*)d_in[4];
    const float* b_q = (const float*)d_in[5];
    const float* w_k = (const float*)d_in[6];
    const float* b_k = (const float*)d_in[7];
    const float* w_v = (const float*)d_in[8];
    const float* b_v = (const float*)d_in[9];
    const float* w_o = (const float*)d_in[10];
    const float* b_o = (const float*)d_in[11];
    float* out = (float*)d_out;

    dim3 gq(DD / 128, MM / 128, 3);          // (8, 32, 3) fused QKV
    qkv_gemm<<<gq, 256>>>(query, key_, value, w_q, w_k, w_v, b_q, b_k, b_v);

    dim3 ga(LL / 128, BB * HH);              // (16, 32)
    flash_attn<<<ga, 128>>>();

    dim3 gg(DD / 128, MM / 128);             // (8, 32)
    out_gemm<<<gg, 256>>>(w_o, b_o, out);
}

// round 6
// speedup vs baseline: 1.7830x; 1.7830x over previous
#include <cuda_runtime.h>
#include <cuda_bf16.h>
#include <math_constants.h>

// Problem constants
#define BB 2
#define LL 2048
#define DD 1024
#define HH 16
#define DKK 64
#define MM (BB * LL)          // 4096 rows

// ---------------------------------------------------------------------------
// Helpers (baseline sm_100 features only: ldmatrix sm_75+, bf16 mma sm_80+)
// ---------------------------------------------------------------------------
__device__ __forceinline__ unsigned smem_u32(const void* p) {
    unsigned a;
    asm("{ .reg .u64 t; cvta.to.shared.u64 t, %1; cvt.u32.u64 %0, t; }"
        : "=r"(a) : "l"(p));
    return a;
}
#define SWZ128(o) ((o) ^ (((o) >> 3) & 0x70))

__device__ __forceinline__ void ldmat4(unsigned& r0, unsigned& r1,
                                       unsigned& r2, unsigned& r3, unsigned addr) {
    asm volatile("ldmatrix.sync.aligned.m8n8.x4.shared.b16 {%0,%1,%2,%3}, [%4];"
                 : "=r"(r0), "=r"(r1), "=r"(r2), "=r"(r3) : "r"(addr));
}
__device__ __forceinline__ void mma16816(float* c, const unsigned* a,
                                         unsigned b0, unsigned b1) {
    asm volatile("mma.sync.aligned.m16n8k16.row.col.f32.bf16.bf16.f32 "
                 "{%0,%1,%2,%3}, {%4,%5,%6,%7}, {%8,%9}, {%0,%1,%2,%3};"
                 : "+f"(c[0]), "+f"(c[1]), "+f"(c[2]), "+f"(c[3])
                 : "r"(a[0]), "r"(a[1]), "r"(a[2]), "r"(a[3]), "r"(b0), "r"(b1));
}
__device__ __forceinline__ void split1(float v, __nv_bfloat16& h, __nv_bfloat16& l) {
    h = __float2bfloat16(v);
    l = __float2bfloat16(v - __bfloat162float(h));
}

// ---------------------------------------------------------------------------
// Scratch globals
// ---------------------------------------------------------------------------
__device__ float g_Q[BB * HH * LL * DKK];
__device__ float g_K[BB * HH * LL * DKK];
__device__ float g_V[BB * HH * LL * DKK];

__device__ __nv_bfloat16 g_xh[3 * MM * DD];   // split inputs (q,k,v)
__device__ __nv_bfloat16 g_xl[3 * MM * DD];
__device__ __nv_bfloat16 g_wh[4 * DD * DD];   // split weights (q,k,v,o)
__device__ __nv_bfloat16 g_wl[4 * DD * DD];
__device__ __nv_bfloat16 g_aoh[MM * DD];      // split attention output
__device__ __nv_bfloat16 g_aol[MM * DD];

// ---------------------------------------------------------------------------
// fp32 -> bf16 hi/lo split kernels
// ---------------------------------------------------------------------------
__global__ void cvt_split_x(const float* __restrict__ s0,
                            const float* __restrict__ s1,
                            const float* __restrict__ s2, int n4)
{
    int z = blockIdx.y;
    const float* src = (z == 0) ? s0 : (z == 1) ? s1 : s2;
    __nv_bfloat16* hi = g_xh + (size_t)z * (MM * DD);
    __nv_bfloat16* lo = g_xl + (size_t)z * (MM * DD);

    int i = blockIdx.x * blockDim.x + threadIdx.x;
    if (i >= n4) return;
    float4 v = ((const float4*)src)[i];
    __nv_bfloat16 h0, l0, h1, l1, h2, l2, h3, l3;
    split1(v.x, h0, l0); split1(v.y, h1, l1);
    split1(v.z, h2, l2); split1(v.w, h3, l3);
    __nv_bfloat162* hp = (__nv_bfloat162*)(hi + 4 * (size_t)i);
    __nv_bfloat162* lp = (__nv_bfloat162*)(lo + 4 * (size_t)i);
    hp[0] = __nv_bfloat162(h0, h1); hp[1] = __nv_bfloat162(h2, h3);
    lp[0] = __nv_bfloat162(l0, l1); lp[1] = __nv_bfloat162(l2, l3);
}

__global__ void cvt_split_w(const float* __restrict__ s0,
                            const float* __restrict__ s1,
                            const float* __restrict__ s2,
                            const float* __restrict__ s3, int n4)
{
    int z = blockIdx.y;
    const float* src = (z == 0) ? s0 : (z == 1) ? s1 : (z == 2) ? s2 : s3;
    __nv_bfloat16* hi = g_wh + (size_t)z * (DD * DD);
    __nv_bfloat16* lo = g_wl + (size_t)z * (DD * DD);

    int i = blockIdx.x * blockDim.x + threadIdx.x;
    if (i >= n4) return;
    float4 v = ((const float4*)src)[i];
    __nv_bfloat16 h0, l0, h1, l1, h2, l2, h3, l3;
    split1(v.x, h0, l0); split1(v.y, h1, l1);
    split1(v.z, h2, l2); split1(v.w, h3, l3);
    __nv_bfloat162* hp = (__nv_bfloat162*)(hi + 4 * (size_t)i);
    __nv_bfloat162* lp = (__nv_bfloat162*)(lo + 4 * (size_t)i);
    hp[0] = __nv_bfloat162(h0, h1); hp[1] = __nv_bfloat162(h2, h3);
    lp[0] = __nv_bfloat162(l0, l1); lp[1] = __nv_bfloat162(l2, l3);
}

// ---------------------------------------------------------------------------
// mma.sync GEMM: C[M,N] = A[M,K]*W[N,K]^T + bias, bf16-split (3 passes).
// CTA: 128x128 C-tile, 256 thr = 8 warps (2M x 4N), warp tile 64x32.
// K chunks of 64 bf16 in smem (128B rows, SW128 swizzle -> conflict-free
// ldmatrix). Both A and W are K-contiguous; plain ldmatrix matches the
// row.col fragment layouts for both operands.
// mode 0 = QKV (blockIdx.z selects, scatter fp32 to g_Q/g_K/g_V); mode 3 = O-proj.
// ---------------------------------------------------------------------------
#define TILEB 16384                       // one 128x64 bf16 tile (swizzled)
#define GEMM_SMEM (4 * TILEB + 1024)      // Ah | Al | Bh | Bl (+align slack)

__device__ __forceinline__ void load_tile(char* dst, const __nv_bfloat16* src,
                                          int r0, int kc, int tid)
{
#pragma unroll
    for (int u = 0; u < 4; u++) {
        int idx = u * 256 + tid;          // 0..1023 16B-units
        int r = idx >> 3, c16 = idx & 7;
        unsigned sw = SWZ128((unsigned)(r * 128 + c16 * 16));
        *(uint4*)(dst + sw) =
            *(const uint4*)(src + (size_t)(r0 + r) * DD + kc + c16 * 8);
    }
}

__global__ __launch_bounds__(256) void tc_gemm(
    const float* __restrict__ bias0, const float* __restrict__ bias1,
    const float* __restrict__ bias2, float* __restrict__ outp, int mode)
{
    extern __shared__ char smem_raw[];
    unsigned sb = smem_u32(smem_raw);
    unsigned t0 = (sb + 1023) & ~1023u;   // 1024-aligned base for swizzle
    char* tb = smem_raw + (t0 - sb);

    int tid = threadIdx.x, lane = tid & 31, wid = tid >> 5;
    int wm = wid >> 2, wn = wid & 3;      // warp grid 2(M) x 4(N)
    int q = lane >> 3, i = lane & 7;      // ldmatrix address role
    int khalf = q >> 1;                   // fixed per lane

    const __nv_bfloat16 *Ah, *Al, *Bh, *Bl;
    const float* bias;
    float* qkv_dst = nullptr;
    if (mode == 3) {
        Ah = g_aoh; Al = g_aol;
        Bh = g_wh + 3 * (size_t)DD * DD; Bl = g_wl + 3 * (size_t)DD * DD;
        bias = bias0;
    } else {
        int z = blockIdx.z;
        Ah = g_xh + (size_t)z * MM * DD; Al = g_xl + (size_t)z * MM * DD;
        Bh = g_wh + (size_t)z * DD * DD; Bl = g_wl + (size_t)z * DD * DD;
        bias = (z == 0) ? bias0 : (z == 1) ? bias1 : bias2;
        qkv_dst = (z == 0) ? g_Q : (z == 1) ? g_K : g_V;
    }

    int row0 = blockIdx.y * 128;
    int col0 = blockIdx.x * 128;

    // per-lane fixed smem row byte-offsets for ldmatrix
    unsigned mrowb[4], nrowb[2];
#pragma unroll
    for (int mt = 0; mt < 4; mt++)
        mrowb[mt] = (unsigned)((wm * 64 + mt * 16 + (q & 1) * 8 + i) * 128);
#pragma unroll
    for (int nb = 0; nb < 2; nb++)
        nrowb[nb] = (unsigned)((wn * 32 + nb * 16 + (q & 1) * 8 + i) * 128);

    unsigned tAh = t0, tAl = t0 + TILEB, tBh = t0 + 2 * TILEB, tBl = t0 + 3 * TILEB;

    float acc[4][4][4];
#pragma unroll
    for (int a = 0; a < 4; a++)
#pragma unroll
        for (int b = 0; b < 4; b++)
#pragma unroll
            for (int cc = 0; cc < 4; cc++) acc[a][b][cc] = 0.0f;

    for (int c = 0; c < 16; c++) {
        __syncthreads();
        load_tile(tb,             Ah, row0, c * 64, tid);
        load_tile(tb + TILEB,     Al, row0, c * 64, tid);
        load_tile(tb + 2 * TILEB, Bh, col0, c * 64, tid);
        load_tile(tb + 3 * TILEB, Bl, col0, c * 64, tid);
        __syncthreads();

#pragma unroll
        for (int ks = 0; ks < 4; ks++) {
            unsigned uoff = (unsigned)((ks * 2 + khalf) * 16);
            unsigned ah[4][4], al[4][4], bh[2][4], bl[2][4];
#pragma unroll
            for (int mt = 0; mt < 4; mt++) {
                ldmat4(ah[mt][0], ah[mt][1], ah[mt][2], ah[mt][3],
                       tAh + SWZ128(mrowb[mt] + uoff));
                ldmat4(al[mt][0], al[mt][1], al[mt][2], al[mt][3],
                       tAl + SWZ128(mrowb[mt] + uoff));
            }
#pragma unroll
            for (int nb = 0; nb < 2; nb++) {
                ldmat4(bh[nb][0], bh[nb][1], bh[nb][2], bh[nb][3],
                       tBh + SWZ128(nrowb[nb] + uoff));
                ldmat4(bl[nb][0], bl[nb][1], bl[nb][2], bl[nb][3],
                       tBl + SWZ128(nrowb[nb] + uoff));
            }
#pragma unroll
            for (int mt = 0; mt < 4; mt++)
#pragma unroll
                for (int nt = 0; nt < 4; nt++) {
                    int nb = nt >> 1, sel = nt & 1;
                    mma16816(acc[mt][nt], ah[mt], bh[nb][sel], bh[nb][2 + sel]);
                    mma16816(acc[mt][nt], ah[mt], bl[nb][sel], bl[nb][2 + sel]);
                    mma16816(acc[mt][nt], al[mt], bh[nb][sel], bh[nb][2 + sel]);
                }
        }
    }

    // epilogue: c0,c1 at (r, c),(r, c+1); c2,c3 at (r+8, ...)
    int r_in = lane >> 2, c_in = (lane & 3) * 2;
#pragma unroll
    for (int mt = 0; mt < 4; mt++) {
#pragma unroll
        for (int nt = 0; nt < 4; nt++) {
            int n = col0 + wn * 32 + nt * 8 + c_in;
            float b0v = bias[n], b1v = bias[n + 1];
#pragma unroll
            for (int half = 0; half < 2; half++) {
                int m = row0 + wm * 64 + mt * 16 + r_in + half * 8;
                float v0 = acc[mt][nt][half * 2 + 0] + b0v;
                float v1 = acc[mt][nt][half * 2 + 1] + b1v;
                if (mode == 3) {
                    outp[(size_t)m * DD + n]     = v0;
                    outp[(size_t)m * DD + n + 1] = v1;
                } else {
                    int bb = m >> 11, l = m & 2047;
                    int h0 = n >> 6, d0 = n & 63;
                    int h1 = (n + 1) >> 6, d1 = (n + 1) & 63;
                    qkv_dst[(((size_t)(bb * HH + h0)) * LL + l) * DKK + d0] = v0;
                    qkv_dst[(((size_t)(bb * HH + h1)) * LL + l) * DKK + d1] = v1;
                }
            }
        }
    }
}

// ---------------------------------------------------------------------------
// Flash attention, fp32, causal. 1 thread = 1 query row, 64-thread blocks.
// Heavy q-tiles first. Epilogue writes bf16 hi/lo split directly.
// ---------------------------------------------------------------------------
__global__ __launch_bounds__(64) void flash_attn()
{
    __shared__ __align__(16) float Ks[64][64];
    __shared__ __align__(16) float Vs[64][64];

    int bh  = blockIdx.y;                                  // 0..31
    int qt  = (int)gridDim.x - 1 - (int)blockIdx.x;        // heavy-first
    int tid = threadIdx.x;
    int row = qt * 64 + tid;

    const float* Qrow = g_Q + ((size_t)bh * LL + row) * DKK;
    const float* Kbh  = g_K + (size_t)bh * LL * DKK;
    const float* Vbh  = g_V + (size_t)bh * LL * DKK;

    const float inv_scale = 0.125f;                        // 1/sqrt(64)

    float q[64];
#pragma unroll
    for (int d = 0; d < 64; d++) q[d] = Qrow[d] * inv_scale;

    float o[64];
#pragma unroll
    for (int d = 0; d < 64; d++) o[d] = 0.0f;
    float m = -CUDART_INF_F;
    float l = 0.0f;

    int nkt = qt + 1;

    for (int kt = 0; kt < nkt; kt++) {
        __syncthreads();
        for (int i = tid; i < 64 * 16; i += 64) {
            int r  = i >> 4;
            int c4 = (i & 15) * 4;
            size_t goff = ((size_t)(kt * 64 + r)) * DKK + c4;
            *(float4*)&Ks[r][c4] = *(const float4*)(Kbh + goff);
            *(float4*)&Vs[r][c4] = *(const float4*)(Vbh + goff);
        }
        __syncthreads();

        int jmax = row - kt * 64 + 1;                      // causal
        if (jmax > 64) jmax = 64;

        for (int j = 0; j < jmax; j++) {
            float s = 0.0f;
#pragma unroll
            for (int d = 0; d < 64; d++) s += q[d] * Ks[j][d];

            if (s > m) {                                   // rare after warmup
                float cc = __expf(m - s);
                m = s;
                l *= cc;
#pragma unroll
                for (int d = 0; d < 64; d++) o[d] *= cc;
            }
            float p = __expf(s - m);
            l += p;
#pragma unroll
            for (int d = 0; d < 64; d++) o[d] += p * Vs[j][d];
        }
    }

    float inv_l = 1.0f / l;
    int bb = bh >> 4;
    int h  = bh & 15;
    size_t obase = ((size_t)(bb * LL + row)) * DD + h * DKK;
#pragma unroll
    for (int d = 0; d < 64; d += 2) {
        float v0 = o[d] * inv_l, v1 = o[d + 1] * inv_l;
        __nv_bfloat16 h0, l0, h1, l1;
        split1(v0, h0, l0); split1(v1, h1, l1);
        *(__nv_bfloat162*)(g_aoh + obase + d) = __nv_bfloat162(h0, h1);
        *(__nv_bfloat162*)(g_aol + obase + d) = __nv_bfloat162(l0, l1);
    }
}

// ---------------------------------------------------------------------------
// Launcher
// ---------------------------------------------------------------------------
extern "C" void kernel_launch(void* const* d_in, const int* in_sizes, int n_in,
                              void* d_out, int out_size)
{
    const float* query = (const float*)d_in[0];
    const float* key_  = (const float*)d_in[1];
    const float* value = (const float*)d_in[2];
    // d_in[3] = mask (causal; implemented structurally, not read)
    const float* w_q = (const float*)d_in[4];
    const float* b_q = (const float*)d_in[5];
    const float* w_k = (const float*)d_in[6];
    const float* b_k = (const float*)d_in[7];
    const float* w_v = (const float*)d_in[8];
    const float* b_v = (const float*)d_in[9];
    const float* w_o = (const float*)d_in[10];
    const float* b_o = (const float*)d_in[11];
    float* out = (float*)d_out;

    cudaFuncSetAttribute(tc_gemm, cudaFuncAttributeMaxDynamicSharedMemorySize,
                         GEMM_SMEM);

    int nx4 = (MM * DD) / 4, nw4 = (DD * DD) / 4;
    dim3 gx((nx4 + 255) / 256, 3);
    cvt_split_x<<<gx, 256>>>(query, key_, value, nx4);
    dim3 gw((nw4 + 255) / 256, 4);
    cvt_split_w<<<gw, 256>>>(w_q, w_k, w_v, w_o, nw4);

    dim3 gq(DD / 128, MM / 128, 3);
    tc_gemm<<<gq, 256, GEMM_SMEM>>>(b_q, b_k, b_v, nullptr, 0);

    dim3 ga(LL / 64, BB * HH);
    flash_attn<<<ga, 64>>>();

    dim3 go(DD / 128, MM / 128, 1);
    tc_gemm<<<go, 256, GEMM_SMEM>>>(b_o, nullptr, nullptr, out, 3);
}

// round 7
// speedup vs baseline: 3.6860x; 2.0673x over previous
#include <cuda_runtime.h>
#include <cuda_bf16.h>
#include <math_constants.h>

// Problem constants
#define BB 2
#define LL 2048
#define DD 1024
#define HH 16
#define DKK 64
#define MM (BB * LL)          // 4096 rows

// ---------------------------------------------------------------------------
// Helpers (baseline sm_100: ldmatrix, bf16 mma.sync)
// ---------------------------------------------------------------------------
__device__ __forceinline__ unsigned smem_u32(const void* p) {
    unsigned a;
    asm("{ .reg .u64 t; cvta.to.shared.u64 t, %1; cvt.u32.u64 %0, t; }"
        : "=r"(a) : "l"(p));
    return a;
}
#define SWZ128(o) ((o) ^ (((o) >> 3) & 0x70))

__device__ __forceinline__ void ldmat4(unsigned& r0, unsigned& r1,
                                       unsigned& r2, unsigned& r3, unsigned addr) {
    asm volatile("ldmatrix.sync.aligned.m8n8.x4.shared.b16 {%0,%1,%2,%3}, [%4];"
                 : "=r"(r0), "=r"(r1), "=r"(r2), "=r"(r3) : "r"(addr));
}
__device__ __forceinline__ void ldmat4t(unsigned& r0, unsigned& r1,
                                        unsigned& r2, unsigned& r3, unsigned addr) {
    asm volatile("ldmatrix.sync.aligned.m8n8.x4.trans.shared.b16 {%0,%1,%2,%3}, [%4];"
                 : "=r"(r0), "=r"(r1), "=r"(r2), "=r"(r3) : "r"(addr));
}
__device__ __forceinline__ void mma16816(float* c, const unsigned* a,
                                         unsigned b0, unsigned b1) {
    asm volatile("mma.sync.aligned.m16n8k16.row.col.f32.bf16.bf16.f32 "
                 "{%0,%1,%2,%3}, {%4,%5,%6,%7}, {%8,%9}, {%0,%1,%2,%3};"
                 : "+f"(c[0]), "+f"(c[1]), "+f"(c[2]), "+f"(c[3])
                 : "r"(a[0]), "r"(a[1]), "r"(a[2]), "r"(a[3]), "r"(b0), "r"(b1));
}
__device__ __forceinline__ void split1(float v, __nv_bfloat16& h, __nv_bfloat16& l) {
    h = __float2bfloat16(v);
    l = __float2bfloat16(v - __bfloat162float(h));
}
__device__ __forceinline__ unsigned pack_bf16(float x, float y) {
    __nv_bfloat162 t(__float2bfloat16(x), __float2bfloat16(y));
    return *(unsigned*)&t;
}

// ---------------------------------------------------------------------------
// Scratch globals — Q/K/V kept ONLY as bf16 hi/lo splits
// ---------------------------------------------------------------------------
__device__ __nv_bfloat16 g_qh[BB * HH * LL * DKK];  // [bh][l][d], pre-scaled /8
__device__ __nv_bfloat16 g_ql[BB * HH * LL * DKK];
__device__ __nv_bfloat16 g_kh[BB * HH * LL * DKK];
__device__ __nv_bfloat16 g_kl[BB * HH * LL * DKK];
__device__ __nv_bfloat16 g_vh[BB * HH * LL * DKK];
__device__ __nv_bfloat16 g_vl[BB * HH * LL * DKK];

__device__ __nv_bfloat16 g_xh[3 * MM * DD];   // split inputs (q,k,v)
__device__ __nv_bfloat16 g_xl[3 * MM * DD];
__device__ __nv_bfloat16 g_wh[4 * DD * DD];   // split weights (q,k,v,o)
__device__ __nv_bfloat16 g_wl[4 * DD * DD];
__device__ __nv_bfloat16 g_aoh[MM * DD];      // split attention output
__device__ __nv_bfloat16 g_aol[MM * DD];

// ---------------------------------------------------------------------------
// fp32 -> bf16 hi/lo split kernels
// ---------------------------------------------------------------------------
__global__ void cvt_split_x(const float* __restrict__ s0,
                            const float* __restrict__ s1,
                            const float* __restrict__ s2, int n4)
{
    int z = blockIdx.y;
    const float* src = (z == 0) ? s0 : (z == 1) ? s1 : s2;
    __nv_bfloat16* hi = g_xh + (size_t)z * (MM * DD);
    __nv_bfloat16* lo = g_xl + (size_t)z * (MM * DD);

    int i = blockIdx.x * blockDim.x + threadIdx.x;
    if (i >= n4) return;
    float4 v = ((const float4*)src)[i];
    __nv_bfloat16 h0, l0, h1, l1, h2, l2, h3, l3;
    split1(v.x, h0, l0); split1(v.y, h1, l1);
    split1(v.z, h2, l2); split1(v.w, h3, l3);
    __nv_bfloat162* hp = (__nv_bfloat162*)(hi + 4 * (size_t)i);
    __nv_bfloat162* lp = (__nv_bfloat162*)(lo + 4 * (size_t)i);
    hp[0] = __nv_bfloat162(h0, h1); hp[1] = __nv_bfloat162(h2, h3);
    lp[0] = __nv_bfloat162(l0, l1); lp[1] = __nv_bfloat162(l2, l3);
}

__global__ void cvt_split_w(const float* __restrict__ s0,
                            const float* __restrict__ s1,
                            const float* __restrict__ s2,
                            const float* __restrict__ s3, int n4)
{
    int z = blockIdx.y;
    const float* src = (z == 0) ? s0 : (z == 1) ? s1 : (z == 2) ? s2 : s3;
    __nv_bfloat16* hi = g_wh + (size_t)z * (DD * DD);
    __nv_bfloat16* lo = g_wl + (size_t)z * (DD * DD);

    int i = blockIdx.x * blockDim.x + threadIdx.x;
    if (i >= n4) return;
    float4 v = ((const float4*)src)[i];
    __nv_bfloat16 h0, l0, h1, l1, h2, l2, h3, l3;
    split1(v.x, h0, l0); split1(v.y, h1, l1);
    split1(v.z, h2, l2); split1(v.w, h3, l3);
    __nv_bfloat162* hp = (__nv_bfloat162*)(hi + 4 * (size_t)i);
    __nv_bfloat162* lp = (__nv_bfloat162*)(lo + 4 * (size_t)i);
    hp[0] = __nv_bfloat162(h0, h1); hp[1] = __nv_bfloat162(h2, h3);
    lp[0] = __nv_bfloat162(l0, l1); lp[1] = __nv_bfloat162(l2, l3);
}

// ---------------------------------------------------------------------------
// mma.sync GEMM: C = A*W^T + bias, bf16-split (3 passes). 128x128 CTA tile,
// 8 warps (2Mx4N), warp tile 64x32.  mode 0 = QKV (epilogue splits to bf16
// hi/lo Q/K/V globals, Q pre-scaled by 1/8); mode 3 = output projection.
// ---------------------------------------------------------------------------
#define TILEB 16384
#define GEMM_SMEM (4 * TILEB + 1024)

__device__ __forceinline__ void load_tile(char* dst, const __nv_bfloat16* src,
                                          int r0, int kc, int tid)
{
#pragma unroll
    for (int u = 0; u < 4; u++) {
        int idx = u * 256 + tid;
        int r = idx >> 3, c16 = idx & 7;
        unsigned sw = SWZ128((unsigned)(r * 128 + c16 * 16));
        *(uint4*)(dst + sw) =
            *(const uint4*)(src + (size_t)(r0 + r) * DD + kc + c16 * 8);
    }
}

__global__ __launch_bounds__(256) void tc_gemm(
    const float* __restrict__ bias0, const float* __restrict__ bias1,
    const float* __restrict__ bias2, float* __restrict__ outp, int mode)
{
    extern __shared__ char smem_raw[];
    unsigned sb = smem_u32(smem_raw);
    unsigned t0 = (sb + 1023) & ~1023u;
    char* tb = smem_raw + (t0 - sb);

    int tid = threadIdx.x, lane = tid & 31, wid = tid >> 5;
    int wm = wid >> 2, wn = wid & 3;
    int q = lane >> 3, i = lane & 7;
    int khalf = q >> 1;

    const __nv_bfloat16 *Ah, *Al, *Bh, *Bl;
    const float* bias;
    int z = blockIdx.z;
    if (mode == 3) {
        Ah = g_aoh; Al = g_aol;
        Bh = g_wh + 3 * (size_t)DD * DD; Bl = g_wl + 3 * (size_t)DD * DD;
        bias = bias0;
    } else {
        Ah = g_xh + (size_t)z * MM * DD; Al = g_xl + (size_t)z * MM * DD;
        Bh = g_wh + (size_t)z * DD * DD; Bl = g_wl + (size_t)z * DD * DD;
        bias = (z == 0) ? bias0 : (z == 1) ? bias1 : bias2;
    }

    int row0 = blockIdx.y * 128;
    int col0 = blockIdx.x * 128;

    unsigned mrowb[4], nrowb[2];
#pragma unroll
    for (int mt = 0; mt < 4; mt++)
        mrowb[mt] = (unsigned)((wm * 64 + mt * 16 + (q & 1) * 8 + i) * 128);
#pragma unroll
    for (int nb = 0; nb < 2; nb++)
        nrowb[nb] = (unsigned)((wn * 32 + nb * 16 + (q & 1) * 8 + i) * 128);

    unsigned tAh = t0, tAl = t0 + TILEB, tBh = t0 + 2 * TILEB, tBl = t0 + 3 * TILEB;

    float acc[4][4][4];
#pragma unroll
    for (int a = 0; a < 4; a++)
#pragma unroll
        for (int b = 0; b < 4; b++)
#pragma unroll
            for (int cc = 0; cc < 4; cc++) acc[a][b][cc] = 0.0f;

    for (int c = 0; c < 16; c++) {
        __syncthreads();
        load_tile(tb,             Ah, row0, c * 64, tid);
        load_tile(tb + TILEB,     Al, row0, c * 64, tid);
        load_tile(tb + 2 * TILEB, Bh, col0, c * 64, tid);
        load_tile(tb + 3 * TILEB, Bl, col0, c * 64, tid);
        __syncthreads();

#pragma unroll
        for (int ks = 0; ks < 4; ks++) {
            unsigned uoff = (unsigned)((ks * 2 + khalf) * 16);
            unsigned ah[4][4], al[4][4], bh[2][4], bl[2][4];
#pragma unroll
            for (int mt = 0; mt < 4; mt++) {
                ldmat4(ah[mt][0], ah[mt][1], ah[mt][2], ah[mt][3],
                       tAh + SWZ128(mrowb[mt] + uoff));
                ldmat4(al[mt][0], al[mt][1], al[mt][2], al[mt][3],
                       tAl + SWZ128(mrowb[mt] + uoff));
            }
#pragma unroll
            for (int nb = 0; nb < 2; nb++) {
                ldmat4(bh[nb][0], bh[nb][1], bh[nb][2], bh[nb][3],
                       tBh + SWZ128(nrowb[nb] + uoff));
                ldmat4(bl[nb][0], bl[nb][1], bl[nb][2], bl[nb][3],
                       tBl + SWZ128(nrowb[nb] + uoff));
            }
#pragma unroll
            for (int mt = 0; mt < 4; mt++)
#pragma unroll
                for (int nt = 0; nt < 4; nt++) {
                    int nb = nt >> 1, sel = nt & 1;
                    mma16816(acc[mt][nt], ah[mt], bh[nb][sel], bh[nb][2 + sel]);
                    mma16816(acc[mt][nt], ah[mt], bl[nb][sel], bl[nb][2 + sel]);
                    mma16816(acc[mt][nt], al[mt], bh[nb][sel], bh[nb][2 + sel]);
                }
        }
    }

    __nv_bfloat16 *dh = nullptr, *dl = nullptr;
    float qscale = 1.0f;
    if (mode != 3) {
        dh = (z == 0) ? g_qh : (z == 1) ? g_kh : g_vh;
        dl = (z == 0) ? g_ql : (z == 1) ? g_kl : g_vl;
        if (z == 0) qscale = 0.125f;     // fold 1/sqrt(DK) into Q
    }

    int r_in = lane >> 2, c_in = (lane & 3) * 2;
#pragma unroll
    for (int mt = 0; mt < 4; mt++) {
#pragma unroll
        for (int nt = 0; nt < 4; nt++) {
            int n = col0 + wn * 32 + nt * 8 + c_in;
            float b0v = bias[n], b1v = bias[n + 1];
#pragma unroll
            for (int half = 0; half < 2; half++) {
                int m = row0 + wm * 64 + mt * 16 + r_in + half * 8;
                float v0 = acc[mt][nt][half * 2 + 0] + b0v;
                float v1 = acc[mt][nt][half * 2 + 1] + b1v;
                if (mode == 3) {
                    outp[(size_t)m * DD + n]     = v0;
                    outp[(size_t)m * DD + n + 1] = v1;
                } else {
                    v0 *= qscale; v1 *= qscale;
                    int bb = m >> 11, l = m & 2047;
                    int h0 = n >> 6, d0 = n & 63;       // pair stays in one head
                    size_t base = (((size_t)(bb * HH + h0)) * LL + l) * DKK + d0;
                    __nv_bfloat16 h0b, l0b, h1b, l1b;
                    split1(v0, h0b, l0b); split1(v1, h1b, l1b);
                    *(__nv_bfloat162*)(dh + base) = __nv_bfloat162(h0b, h1b);
                    *(__nv_bfloat162*)(dl + base) = __nv_bfloat162(l0b, l1b);
                }
            }
        }
    }
}

// ---------------------------------------------------------------------------
// Tensor-core flash attention (FA2-style), bf16-split, causal.
// CTA: 64 q-rows of one (b,h); 4 warps x 16 rows. K/V chunks of 64 keys.
// S = Qh·Kh + Ql·Kh + Qh·Kl ; P·V = Ph·Vh + Pl·Vh + Ph·Vl (fp32 accum).
// V B-fragments via ldmatrix.trans. Heavy q-tiles launched first.
// ---------------------------------------------------------------------------
__global__ __launch_bounds__(128) void flash_attn_mma()
{
    __shared__ uint4 sbuf[2048];            // 32KB: Kh | Kl | Vh | Vl
    unsigned sB = smem_u32(sbuf);
    const unsigned KH = 0, KL = 8192, VH = 16384, VL = 24576;
    char* sc8 = (char*)sbuf;

    int bh  = blockIdx.y;
    int qt  = (int)gridDim.x - 1 - (int)blockIdx.x;   // heavy-first
    int q0  = qt * 64;
    int tid = threadIdx.x, lane = tid & 31, wm = tid >> 5;
    int q = lane >> 3, i = lane & 7;
    int r_in = lane >> 2, c_in = (lane & 3) * 2;

    const __nv_bfloat16* Kbh = g_kh + (size_t)bh * LL * DKK;
    const __nv_bfloat16* Klb = g_kl + (size_t)bh * LL * DKK;
    const __nv_bfloat16* Vbh = g_vh + (size_t)bh * LL * DKK;
    const __nv_bfloat16* Vlb = g_vl + (size_t)bh * LL * DKK;

    // ---- stage Q tile (64x64) through K buffers, build Q fragments
    {
        const __nv_bfloat16* Qh = g_qh + ((size_t)bh * LL + q0) * DKK;
        const __nv_bfloat16* Ql = g_ql + ((size_t)bh * LL + q0) * DKK;
#pragma unroll
        for (int u = 0; u < 4; u++) {
            int idx = u * 128 + tid;
            int r = idx >> 3, c16 = idx & 7;
            unsigned sw = SWZ128((unsigned)(r * 128 + c16 * 16));
            *(uint4*)(sc8 + KH + sw) = *(const uint4*)(Qh + (size_t)r * DKK + c16 * 8);
            *(uint4*)(sc8 + KL + sw) = *(const uint4*)(Ql + (size_t)r * DKK + c16 * 8);
        }
    }
    __syncthreads();

    unsigned qh[4][4], ql[4][4];
    {
        unsigned mrow = (unsigned)((wm * 16 + (q & 1) * 8 + i) * 128);
#pragma unroll
        for (int kt = 0; kt < 4; kt++) {
            unsigned uoff = (unsigned)(kt * 32 + (q >> 1) * 16);
            ldmat4(qh[kt][0], qh[kt][1], qh[kt][2], qh[kt][3],
                   sB + KH + SWZ128(mrow + uoff));
            ldmat4(ql[kt][0], ql[kt][1], ql[kt][2], ql[kt][3],
                   sB + KL + SWZ128(mrow + uoff));
        }
    }
    __syncthreads();

    float o[8][4];
#pragma unroll
    for (int t = 0; t < 8; t++)
#pragma unroll
        for (int cc = 0; cc < 4; cc++) o[t][cc] = 0.0f;
    float m0 = -CUDART_INF_F, m1 = -CUDART_INF_F, l0 = 0.0f, l1 = 0.0f;

    int qoff0 = wm * 16 + r_in;          // query offset within tile (row of c0/c1)
    int nch = qt + 1;

    for (int ck = 0; ck < nch; ck++) {
        int kb = ck * 64;
        // ---- fill K/V chunk (bf16 hi/lo, swizzled)
#pragma unroll
        for (int u = 0; u < 4; u++) {
            int idx = u * 128 + tid;
            int r = idx >> 3, c16 = idx & 7;
            unsigned sw = SWZ128((unsigned)(r * 128 + c16 * 16));
            size_t goff = (size_t)(kb + r) * DKK + c16 * 8;
            *(uint4*)(sc8 + KH + sw) = *(const uint4*)(Kbh + goff);
            *(uint4*)(sc8 + KL + sw) = *(const uint4*)(Klb + goff);
            *(uint4*)(sc8 + VH + sw) = *(const uint4*)(Vbh + goff);
            *(uint4*)(sc8 + VL + sw) = *(const uint4*)(Vlb + goff);
        }
        __syncthreads();

        // ---- S = Q · K^T   (8 n-tiles of 8 keys, fp32 frags)
        float sc[8][4];
#pragma unroll
        for (int t = 0; t < 8; t++)
#pragma unroll
            for (int cc = 0; cc < 4; cc++) sc[t][cc] = 0.0f;

#pragma unroll
        for (int kt = 0; kt < 4; kt++) {
            unsigned uoff = (unsigned)(kt * 32 + (q >> 1) * 16);
            unsigned kf[4][4], lf[4][4];
#pragma unroll
            for (int nb = 0; nb < 4; nb++) {
                unsigned nrow = (unsigned)((nb * 16 + (q & 1) * 8 + i) * 128);
                ldmat4(kf[nb][0], kf[nb][1], kf[nb][2], kf[nb][3],
                       sB + KH + SWZ128(nrow + uoff));
                ldmat4(lf[nb][0], lf[nb][1], lf[nb][2], lf[nb][3],
                       sB + KL + SWZ128(nrow + uoff));
            }
#pragma unroll
            for (int nb = 0; nb < 4; nb++)
#pragma unroll
                for (int sel = 0; sel < 2; sel++) {
                    int t = 2 * nb + sel;
                    mma16816(sc[t], qh[kt], kf[nb][sel], kf[nb][2 + sel]);
                    mma16816(sc[t], ql[kt], kf[nb][sel], kf[nb][2 + sel]);
                    mma16816(sc[t], qh[kt], lf[nb][sel], lf[nb][2 + sel]);
                }
        }

        // ---- causal mask (diagonal chunk only)
        if (ck == nch - 1) {
#pragma unroll
            for (int t = 0; t < 8; t++) {
                int k0 = t * 8 + c_in;
                if (k0 > qoff0)     sc[t][0] = -1e30f;
                if (k0 + 1 > qoff0) sc[t][1] = -1e30f;
                if (k0 > qoff0 + 8)     sc[t][2] = -1e30f;
                if (k0 + 1 > qoff0 + 8) sc[t][3] = -1e30f;
            }
        }

        // ---- online softmax (rows r_in and r_in+8)
        float mx0 = -CUDART_INF_F, mx1 = -CUDART_INF_F;
#pragma unroll
        for (int t = 0; t < 8; t++) {
            mx0 = fmaxf(mx0, fmaxf(sc[t][0], sc[t][1]));
            mx1 = fmaxf(mx1, fmaxf(sc[t][2], sc[t][3]));
        }
        mx0 = fmaxf(mx0, __shfl_xor_sync(0xffffffffu, mx0, 1));
        mx0 = fmaxf(mx0, __shfl_xor_sync(0xffffffffu, mx0, 2));
        mx1 = fmaxf(mx1, __shfl_xor_sync(0xffffffffu, mx1, 1));
        mx1 = fmaxf(mx1, __shfl_xor_sync(0xffffffffu, mx1, 2));

        float mn0 = fmaxf(m0, mx0), mn1 = fmaxf(m1, mx1);
        float sf0 = __expf(m0 - mn0), sf1 = __expf(m1 - mn1);
        m0 = mn0; m1 = mn1;

        float rs0 = 0.0f, rs1 = 0.0f;
#pragma unroll
        for (int t = 0; t < 8; t++) {
            sc[t][0] = __expf(sc[t][0] - m0);
            sc[t][1] = __expf(sc[t][1] - m0);
            sc[t][2] = __expf(sc[t][2] - m1);
            sc[t][3] = __expf(sc[t][3] - m1);
            rs0 += sc[t][0] + sc[t][1];
            rs1 += sc[t][2] + sc[t][3];
        }
        rs0 += __shfl_xor_sync(0xffffffffu, rs0, 1);
        rs0 += __shfl_xor_sync(0xffffffffu, rs0, 2);
        rs1 += __shfl_xor_sync(0xffffffffu, rs1, 1);
        rs1 += __shfl_xor_sync(0xffffffffu, rs1, 2);
        l0 = l0 * sf0 + rs0;
        l1 = l1 * sf1 + rs1;

#pragma unroll
        for (int t = 0; t < 8; t++) {
            o[t][0] *= sf0; o[t][1] *= sf0;
            o[t][2] *= sf1; o[t][3] *= sf1;
        }

        // ---- P fragments (hi/lo) and P · V
#pragma unroll
        for (int kt = 0; kt < 4; kt++) {
            unsigned ph[4], pl[4];
#pragma unroll
            for (int hsel = 0; hsel < 2; hsel++) {
                float a0 = sc[2 * kt + hsel][0], a1 = sc[2 * kt + hsel][1];
                float a2 = sc[2 * kt + hsel][2], a3 = sc[2 * kt + hsel][3];
                unsigned hp0 = pack_bf16(a0, a1), hp1 = pack_bf16(a2, a3);
                __nv_bfloat162 hb0 = *(__nv_bfloat162*)&hp0;
                __nv_bfloat162 hb1 = *(__nv_bfloat162*)&hp1;
                unsigned lp0 = pack_bf16(a0 - __bfloat162float(hb0.x),
                                         a1 - __bfloat162float(hb0.y));
                unsigned lp1 = pack_bf16(a2 - __bfloat162float(hb1.x),
                                         a3 - __bfloat162float(hb1.y));
                ph[2 * hsel] = hp0; ph[2 * hsel + 1] = hp1;
                pl[2 * hsel] = lp0; pl[2 * hsel + 1] = lp1;
            }
            // V fragments (trans): keys kt*16..+15, d tiles 2db / 2db+1
            unsigned vrow = (unsigned)((kt * 16 + (q & 1) * 8 + i) * 128);
#pragma unroll
            for (int db = 0; db < 4; db++) {
                unsigned uoff = (unsigned)(db * 32 + (q >> 1) * 16);
                unsigned vh0, vh1, vh2, vh3, vl0, vl1, vl2, vl3;
                ldmat4t(vh0, vh1, vh2, vh3, sB + VH + SWZ128(vrow + uoff));
                ldmat4t(vl0, vl1, vl2, vl3, sB + VL + SWZ128(vrow + uoff));
                mma16816(o[2 * db],     ph, vh0, vh1);
                mma16816(o[2 * db],     pl, vh0, vh1);
                mma16816(o[2 * db],     ph, vl0, vl1);
                mma16816(o[2 * db + 1], ph, vh2, vh3);
                mma16816(o[2 * db + 1], pl, vh2, vh3);
                mma16816(o[2 * db + 1], ph, vl2, vl3);
            }
        }
        __syncthreads();
    }

    // ---- epilogue: normalize, split to bf16 hi/lo
    float inv0 = 1.0f / l0, inv1 = 1.0f / l1;
    int bb = bh >> 4, h = bh & 15;
    int row0g = q0 + wm * 16 + r_in;
#pragma unroll
    for (int t = 0; t < 8; t++) {
        int d = t * 8 + c_in;
        float v0 = o[t][0] * inv0, v1 = o[t][1] * inv0;
        float v2 = o[t][2] * inv1, v3 = o[t][3] * inv1;
        size_t b0 = ((size_t)(bb * LL + row0g)) * DD + h * DKK + d;
        size_t b1 = ((size_t)(bb * LL + row0g + 8)) * DD + h * DKK + d;
        __nv_bfloat16 hh, llo;
        __nv_bfloat16 ha, la, hbq, lb;
        split1(v0, ha, la); split1(v1, hh, llo);
        *(__nv_bfloat162*)(g_aoh + b0) = __nv_bfloat162(ha, hh);
        *(__nv_bfloat162*)(g_aol + b0) = __nv_bfloat162(la, llo);
        split1(v2, hbq, lb); split1(v3, hh, llo);
        *(__nv_bfloat162*)(g_aoh + b1) = __nv_bfloat162(hbq, hh);
        *(__nv_bfloat162*)(g_aol + b1) = __nv_bfloat162(lb, llo);
    }
}

// ---------------------------------------------------------------------------
// Launcher
// ---------------------------------------------------------------------------
extern "C" void kernel_launch(void* const* d_in, const int* in_sizes, int n_in,
                              void* d_out, int out_size)
{
    const float* query = (const float*)d_in[0];
    const float* key_  = (const float*)d_in[1];
    const float* value = (const float*)d_in[2];
    // d_in[3] = mask (causal; implemented structurally, not read)
    const float* w_q = (const float*)d_in[4];
    const float* b_q = (const float*)d_in[5];
    const float* w_k = (const float*)d_in[6];
    const float* b_k = (const float*)d_in[7];
    const float* w_v = (const float*)d_in[8];
    const float* b_v = (const float*)d_in[9];
    const float* w_o = (const float*)d_in[10];
    const float* b_o = (const float*)d_in[11];
    float* out = (float*)d_out;

    cudaFuncSetAttribute(tc_gemm, cudaFuncAttributeMaxDynamicSharedMemorySize,
                         GEMM_SMEM);

    int nx4 = (MM * DD) / 4, nw4 = (DD * DD) / 4;
    dim3 gx((nx4 + 255) / 256, 3);
    cvt_split_x<<<gx, 256>>>(query, key_, value, nx4);
    dim3 gw((nw4 + 255) / 256, 4);
    cvt_split_w<<<gw, 256>>>(w_q, w_k, w_v, w_o, nw4);

    dim3 gq(DD / 128, MM / 128, 3);
    tc_gemm<<<gq, 256, GEMM_SMEM>>>(b_q, b_k, b_v, nullptr, 0);

    dim3 ga(LL / 64, BB * HH);
    flash_attn_mma<<<ga, 128>>>();

    dim3 go(DD / 128, MM / 128, 1);
    tc_gemm<<<go, 256, GEMM_SMEM>>>(b_o, nullptr, nullptr, out, 3);
}

// round 8
// speedup vs baseline: 4.7067x; 1.2769x over previous
#include <cuda_runtime.h>
#include <cuda_bf16.h>
#include <math_constants.h>

// Problem constants
#define BB 2
#define LL 2048
#define DD 1024
#define HH 16
#define DKK 64
#define MM (BB * LL)          // 4096 rows

// ---------------------------------------------------------------------------
// Helpers (baseline sm_100: ldmatrix, bf16 mma.sync, cp.async)
// ---------------------------------------------------------------------------
__device__ __forceinline__ unsigned smem_u32(const void* p) {
    unsigned a;
    asm("{ .reg .u64 t; cvta.to.shared.u64 t, %1; cvt.u32.u64 %0, t; }"
        : "=r"(a) : "l"(p));
    return a;
}
#define SWZ128(o) ((o) ^ (((o) >> 3) & 0x70))

#define CP_ASYNC16(dst, src) \
    asm volatile("cp.async.cg.shared.global [%0], [%1], 16;" :: "r"(dst), "l"(src))
#define CP_COMMIT() asm volatile("cp.async.commit_group;" ::: "memory")
#define CP_WAIT0()  asm volatile("cp.async.wait_group 0;" ::: "memory")

__device__ __forceinline__ void ldmat4(unsigned& r0, unsigned& r1,
                                       unsigned& r2, unsigned& r3, unsigned addr) {
    asm volatile("ldmatrix.sync.aligned.m8n8.x4.shared.b16 {%0,%1,%2,%3}, [%4];"
                 : "=r"(r0), "=r"(r1), "=r"(r2), "=r"(r3) : "r"(addr));
}
__device__ __forceinline__ void ldmat4t(unsigned& r0, unsigned& r1,
                                        unsigned& r2, unsigned& r3, unsigned addr) {
    asm volatile("ldmatrix.sync.aligned.m8n8.x4.trans.shared.b16 {%0,%1,%2,%3}, [%4];"
                 : "=r"(r0), "=r"(r1), "=r"(r2), "=r"(r3) : "r"(addr));
}
__device__ __forceinline__ void mma16816(float* c, const unsigned* a,
                                         unsigned b0, unsigned b1) {
    asm volatile("mma.sync.aligned.m16n8k16.row.col.f32.bf16.bf16.f32 "
                 "{%0,%1,%2,%3}, {%4,%5,%6,%7}, {%8,%9}, {%0,%1,%2,%3};"
                 : "+f"(c[0]), "+f"(c[1]), "+f"(c[2]), "+f"(c[3])
                 : "r"(a[0]), "r"(a[1]), "r"(a[2]), "r"(a[3]), "r"(b0), "r"(b1));
}
__device__ __forceinline__ void split1(float v, __nv_bfloat16& h, __nv_bfloat16& l) {
    h = __float2bfloat16(v);
    l = __float2bfloat16(v - __bfloat162float(h));
}
__device__ __forceinline__ unsigned pack_bf16(float x, float y) {
    __nv_bfloat162 t(__float2bfloat16(x), __float2bfloat16(y));
    return *(unsigned*)&t;
}

// ---------------------------------------------------------------------------
// Scratch globals — Q/K/V kept ONLY as bf16 hi/lo splits
// ---------------------------------------------------------------------------
__device__ __nv_bfloat16 g_qh[BB * HH * LL * DKK];  // [bh][l][d], pre-scaled /8
__device__ __nv_bfloat16 g_ql[BB * HH * LL * DKK];
__device__ __nv_bfloat16 g_kh[BB * HH * LL * DKK];
__device__ __nv_bfloat16 g_kl[BB * HH * LL * DKK];
__device__ __nv_bfloat16 g_vh[BB * HH * LL * DKK];
__device__ __nv_bfloat16 g_vl[BB * HH * LL * DKK];

__device__ __nv_bfloat16 g_xh[3 * MM * DD];   // split inputs (q,k,v)
__device__ __nv_bfloat16 g_xl[3 * MM * DD];
__device__ __nv_bfloat16 g_wh[4 * DD * DD];   // split weights (q,k,v,o)
__device__ __nv_bfloat16 g_wl[4 * DD * DD];
__device__ __nv_bfloat16 g_aoh[MM * DD];      // split attention output
__device__ __nv_bfloat16 g_aol[MM * DD];

// ---------------------------------------------------------------------------
// fp32 -> bf16 hi/lo split kernels
// ---------------------------------------------------------------------------
__global__ void cvt_split_x(const float* __restrict__ s0,
                            const float* __restrict__ s1,
                            const float* __restrict__ s2, int n4)
{
    int z = blockIdx.y;
    const float* src = (z == 0) ? s0 : (z == 1) ? s1 : s2;
    __nv_bfloat16* hi = g_xh + (size_t)z * (MM * DD);
    __nv_bfloat16* lo = g_xl + (size_t)z * (MM * DD);

    int i = blockIdx.x * blockDim.x + threadIdx.x;
    if (i >= n4) return;
    float4 v = ((const float4*)src)[i];
    __nv_bfloat16 h0, l0, h1, l1, h2, l2, h3, l3;
    split1(v.x, h0, l0); split1(v.y, h1, l1);
    split1(v.z, h2, l2); split1(v.w, h3, l3);
    __nv_bfloat162* hp = (__nv_bfloat162*)(hi + 4 * (size_t)i);
    __nv_bfloat162* lp = (__nv_bfloat162*)(lo + 4 * (size_t)i);
    hp[0] = __nv_bfloat162(h0, h1); hp[1] = __nv_bfloat162(h2, h3);
    lp[0] = __nv_bfloat162(l0, l1); lp[1] = __nv_bfloat162(l2, l3);
}

__global__ void cvt_split_w(const float* __restrict__ s0,
                            const float* __restrict__ s1,
                            const float* __restrict__ s2,
                            const float* __restrict__ s3, int n4)
{
    int z = blockIdx.y;
    const float* src = (z == 0) ? s0 : (z == 1) ? s1 : (z == 2) ? s2 : s3;
    __nv_bfloat16* hi = g_wh + (size_t)z * (DD * DD);
    __nv_bfloat16* lo = g_wl + (size_t)z * (DD * DD);

    int i = blockIdx.x * blockDim.x + threadIdx.x;
    if (i >= n4) return;
    float4 v = ((const float4*)src)[i];
    __nv_bfloat16 h0, l0, h1, l1, h2, l2, h3, l3;
    split1(v.x, h0, l0); split1(v.y, h1, l1);
    split1(v.z, h2, l2); split1(v.w, h3, l3);
    __nv_bfloat162* hp = (__nv_bfloat162*)(hi + 4 * (size_t)i);
    __nv_bfloat162* lp = (__nv_bfloat162*)(lo + 4 * (size_t)i);
    hp[0] = __nv_bfloat162(h0, h1); hp[1] = __nv_bfloat162(h2, h3);
    lp[0] = __nv_bfloat162(l0, l1); lp[1] = __nv_bfloat162(l2, l3);
}

// ---------------------------------------------------------------------------
// mma.sync GEMM, cp.async double-buffered. 128x128 CTA tile, 8 warps (2Mx4N).
// bf16-split (3 passes). mode 0 = QKV (split-epilogue to Q/K/V hi/lo, Q/8);
// mode 3 = output projection.
// ---------------------------------------------------------------------------
#define TILEB 16384
#define STAGEB (4 * TILEB)
#define GEMM_SMEM (2 * STAGEB + 1024)

__device__ __forceinline__ void load_tile_async(unsigned dstb,
                                                const __nv_bfloat16* src,
                                                int r0, int kc, int tid)
{
#pragma unroll
    for (int u = 0; u < 4; u++) {
        int idx = u * 256 + tid;
        int r = idx >> 3, c16 = idx & 7;
        unsigned sw = SWZ128((unsigned)(r * 128 + c16 * 16));
        CP_ASYNC16(dstb + sw, src + (size_t)(r0 + r) * DD + kc + c16 * 8);
    }
}

__global__ __launch_bounds__(256) void tc_gemm(
    const float* __restrict__ bias0, const float* __restrict__ bias1,
    const float* __restrict__ bias2, float* __restrict__ outp, int mode)
{
    extern __shared__ char smem_raw[];
    unsigned sb = smem_u32(smem_raw);
    unsigned t0 = (sb + 1023) & ~1023u;

    int tid = threadIdx.x, lane = tid & 31, wid = tid >> 5;
    int wm = wid >> 2, wn = wid & 3;
    int q = lane >> 3, i = lane & 7;
    int khalf = q >> 1;

    const __nv_bfloat16 *Ah, *Al, *Bh, *Bl;
    const float* bias;
    int z = blockIdx.z;
    if (mode == 3) {
        Ah = g_aoh; Al = g_aol;
        Bh = g_wh + 3 * (size_t)DD * DD; Bl = g_wl + 3 * (size_t)DD * DD;
        bias = bias0;
    } else {
        Ah = g_xh + (size_t)z * MM * DD; Al = g_xl + (size_t)z * MM * DD;
        Bh = g_wh + (size_t)z * DD * DD; Bl = g_wl + (size_t)z * DD * DD;
        bias = (z == 0) ? bias0 : (z == 1) ? bias1 : bias2;
    }

    int row0 = blockIdx.y * 128;
    int col0 = blockIdx.x * 128;

    unsigned mrowb[4], nrowb[2];
#pragma unroll
    for (int mt = 0; mt < 4; mt++)
        mrowb[mt] = (unsigned)((wm * 64 + mt * 16 + (q & 1) * 8 + i) * 128);
#pragma unroll
    for (int nb = 0; nb < 2; nb++)
        nrowb[nb] = (unsigned)((wn * 32 + nb * 16 + (q & 1) * 8 + i) * 128);

    float acc[4][4][4];
#pragma unroll
    for (int a = 0; a < 4; a++)
#pragma unroll
        for (int b = 0; b < 4; b++)
#pragma unroll
            for (int cc = 0; cc < 4; cc++) acc[a][b][cc] = 0.0f;

    // prologue: load chunk 0 into stage 0
    {
        unsigned st = t0;
        load_tile_async(st,             Ah, row0, 0, tid);
        load_tile_async(st + TILEB,     Al, row0, 0, tid);
        load_tile_async(st + 2 * TILEB, Bh, col0, 0, tid);
        load_tile_async(st + 3 * TILEB, Bl, col0, 0, tid);
        CP_COMMIT();
    }

    for (int c = 0; c < 16; c++) {
        CP_WAIT0();
        __syncthreads();                 // chunk c resident; stage c+1&1 free

        if (c + 1 < 16) {
            unsigned st = t0 + ((c + 1) & 1) * STAGEB;
            load_tile_async(st,             Ah, row0, (c + 1) * 64, tid);
            load_tile_async(st + TILEB,     Al, row0, (c + 1) * 64, tid);
            load_tile_async(st + 2 * TILEB, Bh, col0, (c + 1) * 64, tid);
            load_tile_async(st + 3 * TILEB, Bl, col0, (c + 1) * 64, tid);
            CP_COMMIT();
        }

        unsigned sa = t0 + (c & 1) * STAGEB;
        unsigned tAh = sa, tAl = sa + TILEB, tBh = sa + 2 * TILEB, tBl = sa + 3 * TILEB;

#pragma unroll
        for (int ks = 0; ks < 4; ks++) {
            unsigned uoff = (unsigned)((ks * 2 + khalf) * 16);
            unsigned ah[4][4], al[4][4], bh[2][4], bl[2][4];
#pragma unroll
            for (int mt = 0; mt < 4; mt++) {
                ldmat4(ah[mt][0], ah[mt][1], ah[mt][2], ah[mt][3],
                       tAh + SWZ128(mrowb[mt] + uoff));
                ldmat4(al[mt][0], al[mt][1], al[mt][2], al[mt][3],
                       tAl + SWZ128(mrowb[mt] + uoff));
            }
#pragma unroll
            for (int nb = 0; nb < 2; nb++) {
                ldmat4(bh[nb][0], bh[nb][1], bh[nb][2], bh[nb][3],
                       tBh + SWZ128(nrowb[nb] + uoff));
                ldmat4(bl[nb][0], bl[nb][1], bl[nb][2], bl[nb][3],
                       tBl + SWZ128(nrowb[nb] + uoff));
            }
#pragma unroll
            for (int mt = 0; mt < 4; mt++)
#pragma unroll
                for (int nt = 0; nt < 4; nt++) {
                    int nb = nt >> 1, sel = nt & 1;
                    mma16816(acc[mt][nt], ah[mt], bh[nb][sel], bh[nb][2 + sel]);
                    mma16816(acc[mt][nt], ah[mt], bl[nb][sel], bl[nb][2 + sel]);
                    mma16816(acc[mt][nt], al[mt], bh[nb][sel], bh[nb][2 + sel]);
                }
        }
        __syncthreads();                 // compute done before stage reuse
    }

    __nv_bfloat16 *dh = nullptr, *dl = nullptr;
    float qscale = 1.0f;
    if (mode != 3) {
        dh = (z == 0) ? g_qh : (z == 1) ? g_kh : g_vh;
        dl = (z == 0) ? g_ql : (z == 1) ? g_kl : g_vl;
        if (z == 0) qscale = 0.125f;     // fold 1/sqrt(DK) into Q
    }

    int r_in = lane >> 2, c_in = (lane & 3) * 2;
#pragma unroll
    for (int mt = 0; mt < 4; mt++) {
#pragma unroll
        for (int nt = 0; nt < 4; nt++) {
            int n = col0 + wn * 32 + nt * 8 + c_in;
            float b0v = bias[n], b1v = bias[n + 1];
#pragma unroll
            for (int half = 0; half < 2; half++) {
                int m = row0 + wm * 64 + mt * 16 + r_in + half * 8;
                float v0 = acc[mt][nt][half * 2 + 0] + b0v;
                float v1 = acc[mt][nt][half * 2 + 1] + b1v;
                if (mode == 3) {
                    outp[(size_t)m * DD + n]     = v0;
                    outp[(size_t)m * DD + n + 1] = v1;
                } else {
                    v0 *= qscale; v1 *= qscale;
                    int bb = m >> 11, l = m & 2047;
                    int h0 = n >> 6, d0 = n & 63;
                    size_t base = (((size_t)(bb * HH + h0)) * LL + l) * DKK + d0;
                    __nv_bfloat16 h0b, l0b, h1b, l1b;
                    split1(v0, h0b, l0b); split1(v1, h1b, l1b);
                    *(__nv_bfloat162*)(dh + base) = __nv_bfloat162(h0b, h1b);
                    *(__nv_bfloat162*)(dl + base) = __nv_bfloat162(l0b, l1b);
                }
            }
        }
    }
}

// ---------------------------------------------------------------------------
// Tensor-core flash attention, bf16-split, causal, cp.async double-buffered
// K/V chunks. CTA: 64 q-rows x one (b,h); 4 warps. Heavy q-tiles first.
// ---------------------------------------------------------------------------
#define ATT_STAGE 32768
#define ATT_SMEM (2 * ATT_STAGE + 1024)

__global__ __launch_bounds__(128) void flash_attn_mma()
{
    extern __shared__ char smem_raw[];
    unsigned sbr = smem_u32(smem_raw);
    unsigned sB = (sbr + 1023) & ~1023u;
    char* sc8 = smem_raw + (sB - sbr);
    const unsigned KH = 0, KL = 8192, VH = 16384, VL = 24576;

    int bh  = blockIdx.y;
    int qt  = (int)gridDim.x - 1 - (int)blockIdx.x;   // heavy-first
    int q0  = qt * 64;
    int tid = threadIdx.x, lane = tid & 31, wm = tid >> 5;
    int q = lane >> 3, i = lane & 7;
    int r_in = lane >> 2, c_in = (lane & 3) * 2;

    const __nv_bfloat16* Kbh = g_kh + (size_t)bh * LL * DKK;
    const __nv_bfloat16* Klb = g_kl + (size_t)bh * LL * DKK;
    const __nv_bfloat16* Vbh = g_vh + (size_t)bh * LL * DKK;
    const __nv_bfloat16* Vlb = g_vl + (size_t)bh * LL * DKK;

    // ---- stage Q tile through stage-0 K region, build Q fragments
    {
        const __nv_bfloat16* Qh = g_qh + ((size_t)bh * LL + q0) * DKK;
        const __nv_bfloat16* Ql = g_ql + ((size_t)bh * LL + q0) * DKK;
#pragma unroll
        for (int u = 0; u < 4; u++) {
            int idx = u * 128 + tid;
            int r = idx >> 3, c16 = idx & 7;
            unsigned sw = SWZ128((unsigned)(r * 128 + c16 * 16));
            *(uint4*)(sc8 + KH + sw) = *(const uint4*)(Qh + (size_t)r * DKK + c16 * 8);
            *(uint4*)(sc8 + KL + sw) = *(const uint4*)(Ql + (size_t)r * DKK + c16 * 8);
        }
    }
    __syncthreads();

    unsigned qh[4][4], ql[4][4];
    {
        unsigned mrow = (unsigned)((wm * 16 + (q & 1) * 8 + i) * 128);
#pragma unroll
        for (int kt = 0; kt < 4; kt++) {
            unsigned uoff = (unsigned)(kt * 32 + (q >> 1) * 16);
            ldmat4(qh[kt][0], qh[kt][1], qh[kt][2], qh[kt][3],
                   sB + KH + SWZ128(mrow + uoff));
            ldmat4(ql[kt][0], ql[kt][1], ql[kt][2], ql[kt][3],
                   sB + KL + SWZ128(mrow + uoff));
        }
    }
    __syncthreads();

    float o[8][4];
#pragma unroll
    for (int t = 0; t < 8; t++)
#pragma unroll
        for (int cc = 0; cc < 4; cc++) o[t][cc] = 0.0f;
    float m0 = -CUDART_INF_F, m1 = -CUDART_INF_F, l0 = 0.0f, l1 = 0.0f;

    int qoff0 = wm * 16 + r_in;
    int nch = qt + 1;

    // prologue: async-load chunk 0 into stage 0
    {
#pragma unroll
        for (int u = 0; u < 4; u++) {
            int idx = u * 128 + tid;
            int r = idx >> 3, c16 = idx & 7;
            unsigned sw = SWZ128((unsigned)(r * 128 + c16 * 16));
            size_t goff = (size_t)r * DKK + c16 * 8;
            CP_ASYNC16(sB + KH + sw, Kbh + goff);
            CP_ASYNC16(sB + KL + sw, Klb + goff);
            CP_ASYNC16(sB + VH + sw, Vbh + goff);
            CP_ASYNC16(sB + VL + sw, Vlb + goff);
        }
        CP_COMMIT();
    }

    for (int ck = 0; ck < nch; ck++) {
        CP_WAIT0();
        __syncthreads();                 // chunk ck resident, other stage free

        if (ck + 1 < nch) {
            unsigned st = sB + ((ck + 1) & 1) * ATT_STAGE;
            int kb = (ck + 1) * 64;
#pragma unroll
            for (int u = 0; u < 4; u++) {
                int idx = u * 128 + tid;
                int r = idx >> 3, c16 = idx & 7;
                unsigned sw = SWZ128((unsigned)(r * 128 + c16 * 16));
                size_t goff = (size_t)(kb + r) * DKK + c16 * 8;
                CP_ASYNC16(st + KH + sw, Kbh + goff);
                CP_ASYNC16(st + KL + sw, Klb + goff);
                CP_ASYNC16(st + VH + sw, Vbh + goff);
                CP_ASYNC16(st + VL + sw, Vlb + goff);
            }
            CP_COMMIT();
        }

        unsigned stg = sB + (ck & 1) * ATT_STAGE;

        // ---- S = Q · K^T
        float sc[8][4];
#pragma unroll
        for (int t = 0; t < 8; t++)
#pragma unroll
            for (int cc = 0; cc < 4; cc++) sc[t][cc] = 0.0f;

#pragma unroll
        for (int kt = 0; kt < 4; kt++) {
            unsigned uoff = (unsigned)(kt * 32 + (q >> 1) * 16);
            unsigned kf[4][4], lf[4][4];
#pragma unroll
            for (int nb = 0; nb < 4; nb++) {
                unsigned nrow = (unsigned)((nb * 16 + (q & 1) * 8 + i) * 128);
                ldmat4(kf[nb][0], kf[nb][1], kf[nb][2], kf[nb][3],
                       stg + KH + SWZ128(nrow + uoff));
                ldmat4(lf[nb][0], lf[nb][1], lf[nb][2], lf[nb][3],
                       stg + KL + SWZ128(nrow + uoff));
            }
#pragma unroll
            for (int nb = 0; nb < 4; nb++)
#pragma unroll
                for (int sel = 0; sel < 2; sel++) {
                    int t = 2 * nb + sel;
                    mma16816(sc[t], qh[kt], kf[nb][sel], kf[nb][2 + sel]);
                    mma16816(sc[t], ql[kt], kf[nb][sel], kf[nb][2 + sel]);
                    mma16816(sc[t], qh[kt], lf[nb][sel], lf[nb][2 + sel]);
                }
        }

        // ---- causal mask (diagonal chunk only)
        if (ck == nch - 1) {
#pragma unroll
            for (int t = 0; t < 8; t++) {
                int k0 = t * 8 + c_in;
                if (k0 > qoff0)     sc[t][0] = -1e30f;
                if (k0 + 1 > qoff0) sc[t][1] = -1e30f;
                if (k0 > qoff0 + 8)     sc[t][2] = -1e30f;
                if (k0 + 1 > qoff0 + 8) sc[t][3] = -1e30f;
            }
        }

        // ---- online softmax
        float mx0 = -CUDART_INF_F, mx1 = -CUDART_INF_F;
#pragma unroll
        for (int t = 0; t < 8; t++) {
            mx0 = fmaxf(mx0, fmaxf(sc[t][0], sc[t][1]));
            mx1 = fmaxf(mx1, fmaxf(sc[t][2], sc[t][3]));
        }
        mx0 = fmaxf(mx0, __shfl_xor_sync(0xffffffffu, mx0, 1));
        mx0 = fmaxf(mx0, __shfl_xor_sync(0xffffffffu, mx0, 2));
        mx1 = fmaxf(mx1, __shfl_xor_sync(0xffffffffu, mx1, 1));
        mx1 = fmaxf(mx1, __shfl_xor_sync(0xffffffffu, mx1, 2));

        float mn0 = fmaxf(m0, mx0), mn1 = fmaxf(m1, mx1);
        float sf0 = __expf(m0 - mn0), sf1 = __expf(m1 - mn1);
        m0 = mn0; m1 = mn1;

        float rs0 = 0.0f, rs1 = 0.0f;
#pragma unroll
        for (int t = 0; t < 8; t++) {
            sc[t][0] = __expf(sc[t][0] - m0);
            sc[t][1] = __expf(sc[t][1] - m0);
            sc[t][2] = __expf(sc[t][2] - m1);
            sc[t][3] = __expf(sc[t][3] - m1);
            rs0 += sc[t][0] + sc[t][1];
            rs1 += sc[t][2] + sc[t][3];
        }
        rs0 += __shfl_xor_sync(0xffffffffu, rs0, 1);
        rs0 += __shfl_xor_sync(0xffffffffu, rs0, 2);
        rs1 += __shfl_xor_sync(0xffffffffu, rs1, 1);
        rs1 += __shfl_xor_sync(0xffffffffu, rs1, 2);
        l0 = l0 * sf0 + rs0;
        l1 = l1 * sf1 + rs1;

#pragma unroll
        for (int t = 0; t < 8; t++) {
            o[t][0] *= sf0; o[t][1] *= sf0;
            o[t][2] *= sf1; o[t][3] *= sf1;
        }

        // ---- P fragments (hi/lo) and P · V
#pragma unroll
        for (int kt = 0; kt < 4; kt++) {
            unsigned ph[4], pl[4];
#pragma unroll
            for (int hsel = 0; hsel < 2; hsel++) {
                float a0 = sc[2 * kt + hsel][0], a1 = sc[2 * kt + hsel][1];
                float a2 = sc[2 * kt + hsel][2], a3 = sc[2 * kt + hsel][3];
                unsigned hp0 = pack_bf16(a0, a1), hp1 = pack_bf16(a2, a3);
                __nv_bfloat162 hb0 = *(__nv_bfloat162*)&hp0;
                __nv_bfloat162 hb1 = *(__nv_bfloat162*)&hp1;
                unsigned lp0 = pack_bf16(a0 - __bfloat162float(hb0.x),
                                         a1 - __bfloat162float(hb0.y));
                unsigned lp1 = pack_bf16(a2 - __bfloat162float(hb1.x),
                                         a3 - __bfloat162float(hb1.y));
                ph[2 * hsel] = hp0; ph[2 * hsel + 1] = hp1;
                pl[2 * hsel] = lp0; pl[2 * hsel + 1] = lp1;
            }
            unsigned vrow = (unsigned)((kt * 16 + (q & 1) * 8 + i) * 128);
#pragma unroll
            for (int db = 0; db < 4; db++) {
                unsigned uoff = (unsigned)(db * 32 + (q >> 1) * 16);
                unsigned vh0, vh1, vh2, vh3, vl0, vl1, vl2, vl3;
                ldmat4t(vh0, vh1, vh2, vh3, stg + VH + SWZ128(vrow + uoff));
                ldmat4t(vl0, vl1, vl2, vl3, stg + VL + SWZ128(vrow + uoff));
                mma16816(o[2 * db],     ph, vh0, vh1);
                mma16816(o[2 * db],     pl, vh0, vh1);
                mma16816(o[2 * db],     ph, vl0, vl1);
                mma16816(o[2 * db + 1], ph, vh2, vh3);
                mma16816(o[2 * db + 1], pl, vh2, vh3);
                mma16816(o[2 * db + 1], ph, vl2, vl3);
            }
        }
        __syncthreads();
    }

    // ---- epilogue: normalize, split to bf16 hi/lo
    float inv0 = 1.0f / l0, inv1 = 1.0f / l1;
    int bb = bh >> 4, h = bh & 15;
    int row0g = q0 + wm * 16 + r_in;
#pragma unroll
    for (int t = 0; t < 8; t++) {
        int d = t * 8 + c_in;
        float v0 = o[t][0] * inv0, v1 = o[t][1] * inv0;
        float v2 = o[t][2] * inv1, v3 = o[t][3] * inv1;
        size_t b0 = ((size_t)(bb * LL + row0g)) * DD + h * DKK + d;
        size_t b1 = ((size_t)(bb * LL + row0g + 8)) * DD + h * DKK + d;
        __nv_bfloat16 ha, la, hb2, lb2;
        split1(v0, ha, la); split1(v1, hb2, lb2);
        *(__nv_bfloat162*)(g_aoh + b0) = __nv_bfloat162(ha, hb2);
        *(__nv_bfloat162*)(g_aol + b0) = __nv_bfloat162(la, lb2);
        split1(v2, ha, la); split1(v3, hb2, lb2);
        *(__nv_bfloat162*)(g_aoh + b1) = __nv_bfloat162(ha, hb2);
        *(__nv_bfloat162*)(g_aol + b1) = __nv_bfloat162(la, lb2);
    }
}

// ---------------------------------------------------------------------------
// Launcher
// ---------------------------------------------------------------------------
extern "C" void kernel_launch(void* const* d_in, const int* in_sizes, int n_in,
                              void* d_out, int out_size)
{
    const float* query = (const float*)d_in[0];
    const float* key_  = (const float*)d_in[1];
    const float* value = (const float*)d_in[2];
    // d_in[3] = mask (causal; implemented structurally, not read)
    const float* w_q = (const float*)d_in[4];
    const float* b_q = (const float*)d_in[5];
    const float* w_k = (const float*)d_in[6];
    const float* b_k = (const float*)d_in[7];
    const float* w_v = (const float*)d_in[8];
    const float* b_v = (const float*)d_in[9];
    const float* w_o = (const float*)d_in[10];
    const float* b_o = (const float*)d_in[11];
    float* out = (float*)d_out;

    cudaFuncSetAttribute(tc_gemm, cudaFuncAttributeMaxDynamicSharedMemorySize,
                         GEMM_SMEM);
    cudaFuncSetAttribute(flash_attn_mma, cudaFuncAttributeMaxDynamicSharedMemorySize,
                         ATT_SMEM);

    int nx4 = (MM * DD) / 4, nw4 = (DD * DD) / 4;
    dim3 gx((nx4 + 255) / 256, 3);
    cvt_split_x<<<gx, 256>>>(query, key_, value, nx4);
    dim3 gw((nw4 + 255) / 256, 4);
    cvt_split_w<<<gw, 256>>>(w_q, w_k, w_v, w_o, nw4);

    dim3 gq(DD / 128, MM / 128, 3);
    tc_gemm<<<gq, 256, GEMM_SMEM>>>(b_q, b_k, b_v, nullptr, 0);

    dim3 ga(LL / 64, BB * HH);
    flash_attn_mma<<<ga, 128, ATT_SMEM>>>();

    dim3 go(DD / 128, MM / 128, 1);
    tc_gemm<<<go, 256, GEMM_SMEM>>>(b_o, nullptr, nullptr, out, 3);
}

// round 9
// speedup vs baseline: 5.1001x; 1.0836x over previous
#include <cuda_runtime.h>
#include <cuda_bf16.h>
#include <math_constants.h>

// Problem constants
#define BB 2
#define LL 2048
#define DD 1024
#define HH 16
#define DKK 64
#define MM (BB * LL)          // 4096 rows

#define NCTA_ATT 444          // 3 CTAs/SM x 148 SMs
#define NITEMS   1024         // 32 bh x 32 q-tiles

// ---------------------------------------------------------------------------
// Helpers (baseline sm_100: ldmatrix, bf16 mma.sync, cp.async)
// ---------------------------------------------------------------------------
__device__ __forceinline__ unsigned smem_u32(const void* p) {
    unsigned a;
    asm("{ .reg .u64 t; cvta.to.shared.u64 t, %1; cvt.u32.u64 %0, t; }"
        : "=r"(a) : "l"(p));
    return a;
}
#define SWZ128(o) ((o) ^ (((o) >> 3) & 0x70))

#define CP_ASYNC16(dst, src) \
    asm volatile("cp.async.cg.shared.global [%0], [%1], 16;" :: "r"(dst), "l"(src))
#define CP_COMMIT() asm volatile("cp.async.commit_group;" ::: "memory")
#define CP_WAIT0()  asm volatile("cp.async.wait_group 0;" ::: "memory")

__device__ __forceinline__ void ldmat4(unsigned& r0, unsigned& r1,
                                       unsigned& r2, unsigned& r3, unsigned addr) {
    asm volatile("ldmatrix.sync.aligned.m8n8.x4.shared.b16 {%0,%1,%2,%3}, [%4];"
                 : "=r"(r0), "=r"(r1), "=r"(r2), "=r"(r3) : "r"(addr));
}
__device__ __forceinline__ void ldmat4t(unsigned& r0, unsigned& r1,
                                        unsigned& r2, unsigned& r3, unsigned addr) {
    asm volatile("ldmatrix.sync.aligned.m8n8.x4.trans.shared.b16 {%0,%1,%2,%3}, [%4];"
                 : "=r"(r0), "=r"(r1), "=r"(r2), "=r"(r3) : "r"(addr));
}
__device__ __forceinline__ void mma16816(float* c, const unsigned* a,
                                         unsigned b0, unsigned b1) {
    asm volatile("mma.sync.aligned.m16n8k16.row.col.f32.bf16.bf16.f32 "
                 "{%0,%1,%2,%3}, {%4,%5,%6,%7}, {%8,%9}, {%0,%1,%2,%3};"
                 : "+f"(c[0]), "+f"(c[1]), "+f"(c[2]), "+f"(c[3])
                 : "r"(a[0]), "r"(a[1]), "r"(a[2]), "r"(a[3]), "r"(b0), "r"(b1));
}
__device__ __forceinline__ void split1(float v, __nv_bfloat16& h, __nv_bfloat16& l) {
    h = __float2bfloat16(v);
    l = __float2bfloat16(v - __bfloat162float(h));
}
__device__ __forceinline__ unsigned pack_bf16(float x, float y) {
    __nv_bfloat162 t(__float2bfloat16(x), __float2bfloat16(y));
    return *(unsigned*)&t;
}

// ---------------------------------------------------------------------------
// Scratch globals — Q/K/V kept ONLY as bf16 hi/lo splits
// ---------------------------------------------------------------------------
__device__ __nv_bfloat16 g_qh[BB * HH * LL * DKK];  // [bh][l][d], scaled /8*log2e
__device__ __nv_bfloat16 g_ql[BB * HH * LL * DKK];
__device__ __nv_bfloat16 g_kh[BB * HH * LL * DKK];
__device__ __nv_bfloat16 g_kl[BB * HH * LL * DKK];
__device__ __nv_bfloat16 g_vh[BB * HH * LL * DKK];
__device__ __nv_bfloat16 g_vl[BB * HH * LL * DKK];

__device__ __nv_bfloat16 g_xh[3 * MM * DD];   // split inputs (q,k,v)
__device__ __nv_bfloat16 g_xl[3 * MM * DD];
__device__ __nv_bfloat16 g_wh[4 * DD * DD];   // split weights (q,k,v,o)
__device__ __nv_bfloat16 g_wl[4 * DD * DD];
__device__ __nv_bfloat16 g_aoh[MM * DD];      // split attention output
__device__ __nv_bfloat16 g_aol[MM * DD];

__device__ int g_ctr;                         // attention work-steal counter

__global__ void reset_ctr() { g_ctr = NCTA_ATT; }

// ---------------------------------------------------------------------------
// fp32 -> bf16 hi/lo split kernels
// ---------------------------------------------------------------------------
__global__ void cvt_split_x(const float* __restrict__ s0,
                            const float* __restrict__ s1,
                            const float* __restrict__ s2, int n4)
{
    int z = blockIdx.y;
    const float* src = (z == 0) ? s0 : (z == 1) ? s1 : s2;
    __nv_bfloat16* hi = g_xh + (size_t)z * (MM * DD);
    __nv_bfloat16* lo = g_xl + (size_t)z * (MM * DD);

    int i = blockIdx.x * blockDim.x + threadIdx.x;
    if (i >= n4) return;
    float4 v = ((const float4*)src)[i];
    __nv_bfloat16 h0, l0, h1, l1, h2, l2, h3, l3;
    split1(v.x, h0, l0); split1(v.y, h1, l1);
    split1(v.z, h2, l2); split1(v.w, h3, l3);
    __nv_bfloat162* hp = (__nv_bfloat162*)(hi + 4 * (size_t)i);
    __nv_bfloat162* lp = (__nv_bfloat162*)(lo + 4 * (size_t)i);
    hp[0] = __nv_bfloat162(h0, h1); hp[1] = __nv_bfloat162(h2, h3);
    lp[0] = __nv_bfloat162(l0, l1); lp[1] = __nv_bfloat162(l2, l3);
}

__global__ void cvt_split_w(const float* __restrict__ s0,
                            const float* __restrict__ s1,
                            const float* __restrict__ s2,
                            const float* __restrict__ s3, int n4)
{
    int z = blockIdx.y;
    const float* src = (z == 0) ? s0 : (z == 1) ? s1 : (z == 2) ? s2 : s3;
    __nv_bfloat16* hi = g_wh + (size_t)z * (DD * DD);
    __nv_bfloat16* lo = g_wl + (size_t)z * (DD * DD);

    int i = blockIdx.x * blockDim.x + threadIdx.x;
    if (i >= n4) return;
    float4 v = ((const float4*)src)[i];
    __nv_bfloat16 h0, l0, h1, l1, h2, l2, h3, l3;
    split1(v.x, h0, l0); split1(v.y, h1, l1);
    split1(v.z, h2, l2); split1(v.w, h3, l3);
    __nv_bfloat162* hp = (__nv_bfloat162*)(hi + 4 * (size_t)i);
    __nv_bfloat162* lp = (__nv_bfloat162*)(lo + 4 * (size_t)i);
    hp[0] = __nv_bfloat162(h0, h1); hp[1] = __nv_bfloat162(h2, h3);
    lp[0] = __nv_bfloat162(l0, l1); lp[1] = __nv_bfloat162(l2, l3);
}

// ---------------------------------------------------------------------------
// mma.sync GEMM, cp.async double-buffered. 128x128 CTA tile, 8 warps (2Mx4N).
// bf16-split (3 passes). mode 0 = QKV (split-epilogue to Q/K/V hi/lo, Q
// scaled by log2e/8); mode 3 = output projection.
// ---------------------------------------------------------------------------
#define TILEB 16384
#define STAGEB (4 * TILEB)
#define GEMM_SMEM (2 * STAGEB + 1024)

__device__ __forceinline__ void load_tile_async(unsigned dstb,
                                                const __nv_bfloat16* src,
                                                int r0, int kc, int tid)
{
#pragma unroll
    for (int u = 0; u < 4; u++) {
        int idx = u * 256 + tid;
        int r = idx >> 3, c16 = idx & 7;
        unsigned sw = SWZ128((unsigned)(r * 128 + c16 * 16));
        CP_ASYNC16(dstb + sw, src + (size_t)(r0 + r) * DD + kc + c16 * 8);
    }
}

__global__ __launch_bounds__(256) void tc_gemm(
    const float* __restrict__ bias0, const float* __restrict__ bias1,
    const float* __restrict__ bias2, float* __restrict__ outp, int mode)
{
    extern __shared__ char smem_raw[];
    unsigned sb = smem_u32(smem_raw);
    unsigned t0 = (sb + 1023) & ~1023u;

    int tid = threadIdx.x, lane = tid & 31, wid = tid >> 5;
    int wm = wid >> 2, wn = wid & 3;
    int q = lane >> 3, i = lane & 7;
    int khalf = q >> 1;

    const __nv_bfloat16 *Ah, *Al, *Bh, *Bl;
    const float* bias;
    int z = blockIdx.z;
    if (mode == 3) {
        Ah = g_aoh; Al = g_aol;
        Bh = g_wh + 3 * (size_t)DD * DD; Bl = g_wl + 3 * (size_t)DD * DD;
        bias = bias0;
    } else {
        Ah = g_xh + (size_t)z * MM * DD; Al = g_xl + (size_t)z * MM * DD;
        Bh = g_wh + (size_t)z * DD * DD; Bl = g_wl + (size_t)z * DD * DD;
        bias = (z == 0) ? bias0 : (z == 1) ? bias1 : bias2;
    }

    int row0 = blockIdx.y * 128;
    int col0 = blockIdx.x * 128;

    unsigned mrowb[4], nrowb[2];
#pragma unroll
    for (int mt = 0; mt < 4; mt++)
        mrowb[mt] = (unsigned)((wm * 64 + mt * 16 + (q & 1) * 8 + i) * 128);
#pragma unroll
    for (int nb = 0; nb < 2; nb++)
        nrowb[nb] = (unsigned)((wn * 32 + nb * 16 + (q & 1) * 8 + i) * 128);

    float acc[4][4][4];
#pragma unroll
    for (int a = 0; a < 4; a++)
#pragma unroll
        for (int b = 0; b < 4; b++)
#pragma unroll
            for (int cc = 0; cc < 4; cc++) acc[a][b][cc] = 0.0f;

    // prologue: load chunk 0 into stage 0
    {
        unsigned st = t0;
        load_tile_async(st,             Ah, row0, 0, tid);
        load_tile_async(st + TILEB,     Al, row0, 0, tid);
        load_tile_async(st + 2 * TILEB, Bh, col0, 0, tid);
        load_tile_async(st + 3 * TILEB, Bl, col0, 0, tid);
        CP_COMMIT();
    }

    for (int c = 0; c < 16; c++) {
        CP_WAIT0();
        __syncthreads();

        if (c + 1 < 16) {
            unsigned st = t0 + ((c + 1) & 1) * STAGEB;
            load_tile_async(st,             Ah, row0, (c + 1) * 64, tid);
            load_tile_async(st + TILEB,     Al, row0, (c + 1) * 64, tid);
            load_tile_async(st + 2 * TILEB, Bh, col0, (c + 1) * 64, tid);
            load_tile_async(st + 3 * TILEB, Bl, col0, (c + 1) * 64, tid);
            CP_COMMIT();
        }

        unsigned sa = t0 + (c & 1) * STAGEB;
        unsigned tAh = sa, tAl = sa + TILEB, tBh = sa + 2 * TILEB, tBl = sa + 3 * TILEB;

#pragma unroll
        for (int ks = 0; ks < 4; ks++) {
            unsigned uoff = (unsigned)((ks * 2 + khalf) * 16);
            unsigned ah[4][4], al[4][4], bh[2][4], bl[2][4];
#pragma unroll
            for (int mt = 0; mt < 4; mt++) {
                ldmat4(ah[mt][0], ah[mt][1], ah[mt][2], ah[mt][3],
                       tAh + SWZ128(mrowb[mt] + uoff));
                ldmat4(al[mt][0], al[mt][1], al[mt][2], al[mt][3],
                       tAl + SWZ128(mrowb[mt] + uoff));
            }
#pragma unroll
            for (int nb = 0; nb < 2; nb++) {
                ldmat4(bh[nb][0], bh[nb][1], bh[nb][2], bh[nb][3],
                       tBh + SWZ128(nrowb[nb] + uoff));
                ldmat4(bl[nb][0], bl[nb][1], bl[nb][2], bl[nb][3],
                       tBl + SWZ128(nrowb[nb] + uoff));
            }
#pragma unroll
            for (int mt = 0; mt < 4; mt++)
#pragma unroll
                for (int nt = 0; nt < 4; nt++) {
                    int nb = nt >> 1, sel = nt & 1;
                    mma16816(acc[mt][nt], ah[mt], bh[nb][sel], bh[nb][2 + sel]);
                    mma16816(acc[mt][nt], ah[mt], bl[nb][sel], bl[nb][2 + sel]);
                    mma16816(acc[mt][nt], al[mt], bh[nb][sel], bh[nb][2 + sel]);
                }
        }
        __syncthreads();
    }

    __nv_bfloat16 *dh = nullptr, *dl = nullptr;
    float qscale = 1.0f;
    if (mode != 3) {
        dh = (z == 0) ? g_qh : (z == 1) ? g_kh : g_vh;
        dl = (z == 0) ? g_ql : (z == 1) ? g_kl : g_vl;
        if (z == 0) qscale = 0.125f * 1.44269504088896f;  // 1/sqrt(DK) * log2(e)
    }

    int r_in = lane >> 2, c_in = (lane & 3) * 2;
#pragma unroll
    for (int mt = 0; mt < 4; mt++) {
#pragma unroll
        for (int nt = 0; nt < 4; nt++) {
            int n = col0 + wn * 32 + nt * 8 + c_in;
            float b0v = bias[n], b1v = bias[n + 1];
#pragma unroll
            for (int half = 0; half < 2; half++) {
                int m = row0 + wm * 64 + mt * 16 + r_in + half * 8;
                float v0 = acc[mt][nt][half * 2 + 0] + b0v;
                float v1 = acc[mt][nt][half * 2 + 1] + b1v;
                if (mode == 3) {
                    outp[(size_t)m * DD + n]     = v0;
                    outp[(size_t)m * DD + n + 1] = v1;
                } else {
                    v0 *= qscale; v1 *= qscale;
                    int bb = m >> 11, l = m & 2047;
                    int h0 = n >> 6, d0 = n & 63;
                    size_t base = (((size_t)(bb * HH + h0)) * LL + l) * DKK + d0;
                    __nv_bfloat16 h0b, l0b, h1b, l1b;
                    split1(v0, h0b, l0b); split1(v1, h1b, l1b);
                    *(__nv_bfloat162*)(dh + base) = __nv_bfloat162(h0b, h1b);
                    *(__nv_bfloat162*)(dl + base) = __nv_bfloat162(l0b, l1b);
                }
            }
        }
    }
}

// ---------------------------------------------------------------------------
// Tensor-core flash attention, bf16-split, causal, cp.async double-buffered,
// exp2-domain softmax, greedy-LPT work stealing over (bh, qt) items sorted
// heavy-first. 444 CTAs, 4 warps each.
// ---------------------------------------------------------------------------
#define ATT_STAGE 32768
#define ATT_SMEM (2 * ATT_STAGE + 1024)

__global__ __launch_bounds__(128) void flash_attn_mma()
{
    extern __shared__ char smem_raw[];
    __shared__ int s_item;
    unsigned sbr = smem_u32(smem_raw);
    unsigned sB = (sbr + 1023) & ~1023u;
    char* sc8 = smem_raw + (sB - sbr);
    const unsigned KH = 0, KL = 8192, VH = 16384, VL = 24576;

    int tid = threadIdx.x, lane = tid & 31, wm = tid >> 5;
    int q = lane >> 3, i = lane & 7;
    int r_in = lane >> 2, c_in = (lane & 3) * 2;

    int item = blockIdx.x;

    while (item < NITEMS) {
        int qt = 31 - (item >> 5);           // heavy-first
        int bh = item & 31;
        int q0 = qt * 64;
        int nch = qt + 1;

        const __nv_bfloat16* Kbh = g_kh + (size_t)bh * LL * DKK;
        const __nv_bfloat16* Klb = g_kl + (size_t)bh * LL * DKK;
        const __nv_bfloat16* Vbh = g_vh + (size_t)bh * LL * DKK;
        const __nv_bfloat16* Vlb = g_vl + (size_t)bh * LL * DKK;

        // ---- stage Q tile through stage-0 K region, build Q fragments
        {
            const __nv_bfloat16* Qh = g_qh + ((size_t)bh * LL + q0) * DKK;
            const __nv_bfloat16* Ql = g_ql + ((size_t)bh * LL + q0) * DKK;
#pragma unroll
            for (int u = 0; u < 4; u++) {
                int idx = u * 128 + tid;
                int r = idx >> 3, c16 = idx & 7;
                unsigned sw = SWZ128((unsigned)(r * 128 + c16 * 16));
                *(uint4*)(sc8 + KH + sw) = *(const uint4*)(Qh + (size_t)r * DKK + c16 * 8);
                *(uint4*)(sc8 + KL + sw) = *(const uint4*)(Ql + (size_t)r * DKK + c16 * 8);
            }
        }
        __syncthreads();

        unsigned qh[4][4], ql[4][4];
        {
            unsigned mrow = (unsigned)((wm * 16 + (q & 1) * 8 + i) * 128);
#pragma unroll
            for (int kt = 0; kt < 4; kt++) {
                unsigned uoff = (unsigned)(kt * 32 + (q >> 1) * 16);
                ldmat4(qh[kt][0], qh[kt][1], qh[kt][2], qh[kt][3],
                       sB + KH + SWZ128(mrow + uoff));
                ldmat4(ql[kt][0], ql[kt][1], ql[kt][2], ql[kt][3],
                       sB + KL + SWZ128(mrow + uoff));
            }
        }
        __syncthreads();

        float o[8][4];
#pragma unroll
        for (int t = 0; t < 8; t++)
#pragma unroll
            for (int cc = 0; cc < 4; cc++) o[t][cc] = 0.0f;
        float m0 = -CUDART_INF_F, m1 = -CUDART_INF_F, l0 = 0.0f, l1 = 0.0f;

        int qoff0 = wm * 16 + r_in;

        // prologue: async-load chunk 0 into stage 0
        {
#pragma unroll
            for (int u = 0; u < 4; u++) {
                int idx = u * 128 + tid;
                int r = idx >> 3, c16 = idx & 7;
                unsigned sw = SWZ128((unsigned)(r * 128 + c16 * 16));
                size_t goff = (size_t)r * DKK + c16 * 8;
                CP_ASYNC16(sB + KH + sw, Kbh + goff);
                CP_ASYNC16(sB + KL + sw, Klb + goff);
                CP_ASYNC16(sB + VH + sw, Vbh + goff);
                CP_ASYNC16(sB + VL + sw, Vlb + goff);
            }
            CP_COMMIT();
        }

        for (int ck = 0; ck < nch; ck++) {
            CP_WAIT0();
            __syncthreads();

            if (ck + 1 < nch) {
                unsigned st = sB + ((ck + 1) & 1) * ATT_STAGE;
                int kb = (ck + 1) * 64;
#pragma unroll
                for (int u = 0; u < 4; u++) {
                    int idx = u * 128 + tid;
                    int r = idx >> 3, c16 = idx & 7;
                    unsigned sw = SWZ128((unsigned)(r * 128 + c16 * 16));
                    size_t goff = (size_t)(kb + r) * DKK + c16 * 8;
                    CP_ASYNC16(st + KH + sw, Kbh + goff);
                    CP_ASYNC16(st + KL + sw, Klb + goff);
                    CP_ASYNC16(st + VH + sw, Vbh + goff);
                    CP_ASYNC16(st + VL + sw, Vlb + goff);
                }
                CP_COMMIT();
            }

            unsigned stg = sB + (ck & 1) * ATT_STAGE;

            // ---- S = Q · K^T (interleaved kf/lf to limit live regs)
            float sc[8][4];
#pragma unroll
            for (int t = 0; t < 8; t++)
#pragma unroll
                for (int cc = 0; cc < 4; cc++) sc[t][cc] = 0.0f;

#pragma unroll
            for (int kt = 0; kt < 4; kt++) {
                unsigned uoff = (unsigned)(kt * 32 + (q >> 1) * 16);
#pragma unroll
                for (int nb = 0; nb < 4; nb++) {
                    unsigned nrow = (unsigned)((nb * 16 + (q & 1) * 8 + i) * 128);
                    unsigned kf[4], lf[4];
                    ldmat4(kf[0], kf[1], kf[2], kf[3],
                           stg + KH + SWZ128(nrow + uoff));
                    ldmat4(lf[0], lf[1], lf[2], lf[3],
                           stg + KL + SWZ128(nrow + uoff));
#pragma unroll
                    for (int sel = 0; sel < 2; sel++) {
                        int t = 2 * nb + sel;
                        mma16816(sc[t], qh[kt], kf[sel], kf[2 + sel]);
                        mma16816(sc[t], ql[kt], kf[sel], kf[2 + sel]);
                        mma16816(sc[t], qh[kt], lf[sel], lf[2 + sel]);
                    }
                }
            }

            // ---- causal mask (diagonal chunk only)
            if (ck == nch - 1) {
#pragma unroll
                for (int t = 0; t < 8; t++) {
                    int k0 = t * 8 + c_in;
                    if (k0 > qoff0)     sc[t][0] = -1e30f;
                    if (k0 + 1 > qoff0) sc[t][1] = -1e30f;
                    if (k0 > qoff0 + 8)     sc[t][2] = -1e30f;
                    if (k0 + 1 > qoff0 + 8) sc[t][3] = -1e30f;
                }
            }

            // ---- online softmax (exp2 domain; log2e folded into Q)
            float mx0 = -CUDART_INF_F, mx1 = -CUDART_INF_F;
#pragma unroll
            for (int t = 0; t < 8; t++) {
                mx0 = fmaxf(mx0, fmaxf(sc[t][0], sc[t][1]));
                mx1 = fmaxf(mx1, fmaxf(sc[t][2], sc[t][3]));
            }
            mx0 = fmaxf(mx0, __shfl_xor_sync(0xffffffffu, mx0, 1));
            mx0 = fmaxf(mx0, __shfl_xor_sync(0xffffffffu, mx0, 2));
            mx1 = fmaxf(mx1, __shfl_xor_sync(0xffffffffu, mx1, 1));
            mx1 = fmaxf(mx1, __shfl_xor_sync(0xffffffffu, mx1, 2));

            float mn0 = fmaxf(m0, mx0), mn1 = fmaxf(m1, mx1);
            float sf0 = exp2f(m0 - mn0), sf1 = exp2f(m1 - mn1);
            m0 = mn0; m1 = mn1;

            float rs0 = 0.0f, rs1 = 0.0f;
#pragma unroll
            for (int t = 0; t < 8; t++) {
                sc[t][0] = exp2f(sc[t][0] - m0);
                sc[t][1] = exp2f(sc[t][1] - m0);
                sc[t][2] = exp2f(sc[t][2] - m1);
                sc[t][3] = exp2f(sc[t][3] - m1);
                rs0 += sc[t][0] + sc[t][1];
                rs1 += sc[t][2] + sc[t][3];
            }
            rs0 += __shfl_xor_sync(0xffffffffu, rs0, 1);
            rs0 += __shfl_xor_sync(0xffffffffu, rs0, 2);
            rs1 += __shfl_xor_sync(0xffffffffu, rs1, 1);
            rs1 += __shfl_xor_sync(0xffffffffu, rs1, 2);
            l0 = l0 * sf0 + rs0;
            l1 = l1 * sf1 + rs1;

#pragma unroll
            for (int t = 0; t < 8; t++) {
                o[t][0] *= sf0; o[t][1] *= sf0;
                o[t][2] *= sf1; o[t][3] *= sf1;
            }

            // ---- P fragments (hi/lo) and P · V
#pragma unroll
            for (int kt = 0; kt < 4; kt++) {
                unsigned ph[4], pl[4];
#pragma unroll
                for (int hsel = 0; hsel < 2; hsel++) {
                    float a0 = sc[2 * kt + hsel][0], a1 = sc[2 * kt + hsel][1];
                    float a2 = sc[2 * kt + hsel][2], a3 = sc[2 * kt + hsel][3];
                    unsigned hp0 = pack_bf16(a0, a1), hp1 = pack_bf16(a2, a3);
                    __nv_bfloat162 hb0 = *(__nv_bfloat162*)&hp0;
                    __nv_bfloat162 hb1 = *(__nv_bfloat162*)&hp1;
                    unsigned lp0 = pack_bf16(a0 - __bfloat162float(hb0.x),
                                             a1 - __bfloat162float(hb0.y));
                    unsigned lp1 = pack_bf16(a2 - __bfloat162float(hb1.x),
                                             a3 - __bfloat162float(hb1.y));
                    ph[2 * hsel] = hp0; ph[2 * hsel + 1] = hp1;
                    pl[2 * hsel] = lp0; pl[2 * hsel + 1] = lp1;
                }
                unsigned vrow = (unsigned)((kt * 16 + (q & 1) * 8 + i) * 128);
#pragma unroll
                for (int db = 0; db < 4; db++) {
                    unsigned uoff = (unsigned)(db * 32 + (q >> 1) * 16);
                    unsigned vh0, vh1, vh2, vh3, vl0, vl1, vl2, vl3;
                    ldmat4t(vh0, vh1, vh2, vh3, stg + VH + SWZ128(vrow + uoff));
                    ldmat4t(vl0, vl1, vl2, vl3, stg + VL + SWZ128(vrow + uoff));
                    mma16816(o[2 * db],     ph, vh0, vh1);
                    mma16816(o[2 * db],     pl, vh0, vh1);
                    mma16816(o[2 * db],     ph, vl0, vl1);
                    mma16816(o[2 * db + 1], ph, vh2, vh3);
                    mma16816(o[2 * db + 1], pl, vh2, vh3);
                    mma16816(o[2 * db + 1], ph, vl2, vl3);
                }
            }
            __syncthreads();
        }

        // ---- epilogue: normalize, split to bf16 hi/lo
        float inv0 = 1.0f / l0, inv1 = 1.0f / l1;
        int bb = bh >> 4, h = bh & 15;
        int row0g = q0 + wm * 16 + r_in;
#pragma unroll
        for (int t = 0; t < 8; t++) {
            int d = t * 8 + c_in;
            float v0 = o[t][0] * inv0, v1 = o[t][1] * inv0;
            float v2 = o[t][2] * inv1, v3 = o[t][3] * inv1;
            size_t b0 = ((size_t)(bb * LL + row0g)) * DD + h * DKK + d;
            size_t b1 = ((size_t)(bb * LL + row0g + 8)) * DD + h * DKK + d;
            __nv_bfloat16 ha, la, hb2, lb2;
            split1(v0, ha, la); split1(v1, hb2, lb2);
            *(__nv_bfloat162*)(g_aoh + b0) = __nv_bfloat162(ha, hb2);
            *(__nv_bfloat162*)(g_aol + b0) = __nv_bfloat162(la, lb2);
            split1(v2, ha, la); split1(v3, hb2, lb2);
            *(__nv_bfloat162*)(g_aoh + b1) = __nv_bfloat162(ha, hb2);
            *(__nv_bfloat162*)(g_aol + b1) = __nv_bfloat162(la, lb2);
        }

        // ---- steal next item
        if (tid == 0) s_item = atomicAdd(&g_ctr, 1);
        __syncthreads();
        item = s_item;
        __syncthreads();
    }
}

// ---------------------------------------------------------------------------
// Launcher
// ---------------------------------------------------------------------------
extern "C" void kernel_launch(void* const* d_in, const int* in_sizes, int n_in,
                              void* d_out, int out_size)
{
    const float* query = (const float*)d_in[0];
    const float* key_  = (const float*)d_in[1];
    const float* value = (const float*)d_in[2];
    // d_in[3] = mask (causal; implemented structurally, not read)
    const float* w_q = (const float*)d_in[4];
    const float* b_q = (const float*)d_in[5];
    const float* w_k = (const float*)d_in[6];
    const float* b_k = (const float*)d_in[7];
    const float* w_v = (const float*)d_in[8];
    const float* b_v = (const float*)d_in[9];
    const float* w_o = (const float*)d_in[10];
    const float* b_o = (const float*)d_in[11];
    float* out = (float*)d_out;

    cudaFuncSetAttribute(tc_gemm, cudaFuncAttributeMaxDynamicSharedMemorySize,
                         GEMM_SMEM);
    cudaFuncSetAttribute(flash_attn_mma, cudaFuncAttributeMaxDynamicSharedMemorySize,
                         ATT_SMEM);

    reset_ctr<<<1, 1>>>();

    int nx4 = (MM * DD) / 4, nw4 = (DD * DD) / 4;
    dim3 gx((nx4 + 255) / 256, 3);
    cvt_split_x<<<gx, 256>>>(query, key_, value, nx4);
    dim3 gw((nw4 + 255) / 256, 4);
    cvt_split_w<<<gw, 256>>>(w_q, w_k, w_v, w_o, nw4);

    dim3 gq(DD / 128, MM / 128, 3);
    tc_gemm<<<gq, 256, GEMM_SMEM>>>(b_q, b_k, b_v, nullptr, 0);

    flash_attn_mma<<<NCTA_ATT, 128, ATT_SMEM>>>();

    dim3 go(DD / 128, MM / 128, 1);
    tc_gemm<<<go, 256, GEMM_SMEM>>>(b_o, nullptr, nullptr, out, 3);
}